// round 15
// baseline (speedup 1.0000x reference)
#include <cuda_runtime.h>
#include <cuda_bf16.h>
#include <math.h>

#define SQ 2048
#define DM 1024
#define NS 4
#define NCH 24
#define NLAY 2
#define NHD 16
#define HHD 1024
#define NEXP 8
#define KSEL 2
#define FF 512
#define VOC 32000
#define MAXENT (SQ*KSEL + NEXP*128)
#define SCRN (16ULL*2048ULL*2048ULL)

typedef unsigned long long ull;
typedef __nv_bfloat16 bf16;

__device__ float g_x[SQ*NS*DM];
__device__ float g_raw[SQ*NCH];
__device__ float g_pre[SQ*NS];
__device__ float g_post[SQ*NS];
__device__ float g_comb[SQ*NS*NS];
__device__ float g_h[SQ*DM];
__device__ float g_q[SQ*HHD];
__device__ float g_k[SQ*HHD];
__device__ float g_v[SQ*HHD];
__device__ float g_scr[SCRN];
__device__ float g_a[SQ*DM];
__device__ float g_cosT[SQ*16];
__device__ float g_sinT[SQ*16];
__device__ float g_inv[SQ];
__device__ int   g_eidx[SQ*KSEL];
__device__ float g_ew[SQ*KSEL];
__device__ int   g_cnt[NEXP];
__device__ int   g_off[NEXP+1];
__device__ int   g_fill[NEXP];
__device__ int   g_etok[MAXENT];
__device__ int   g_eof[SQ*KSEL];
__device__ float g_eg[(size_t)MAXENT*FF];
__device__ float g_eu[(size_t)MAXENT*FF];
__device__ float g_ed[(size_t)MAXENT*DM];
__device__ float g_s1[SQ*FF];
__device__ float g_s2[SQ*FF];
__device__ float t_ahw[NLAY*NCH*4096];
__device__ float t_fhw[NLAY*NCH*4096];
__device__ float t_hw[4*4096];
__device__ bf16 g_ah[SQ*DM],  g_al[SQ*DM];
__device__ bf16 g_aoh[SQ*HHD], g_aol[SQ*HHD];
__device__ bf16 g_s1h[SQ*FF],  g_s1l[SQ*FF];
__device__ bf16 g_egh[(size_t)MAXENT*FF], g_egl[(size_t)MAXENT*FF];
// attention bf16 operands
__device__ bf16 g_qsh[SQ*HHD], g_qsl[SQ*HHD];
__device__ bf16 g_ksh[SQ*HHD], g_ksl[SQ*HHD];
__device__ bf16 g_vth[HHD*SQ], g_vtl[HHD*SQ];
__device__ bf16 g_ph[SCRN], g_pl[SCRN];
__device__ bf16 g_bh[(size_t)VOC*DM], g_bl[(size_t)VOC*DM];
__device__ bf16 twqh[NLAY*DM*HHD], twql[NLAY*DM*HHD];
__device__ bf16 twkh[NLAY*DM*HHD], twkl[NLAY*DM*HHD];
__device__ bf16 twvh[NLAY*DM*HHD], twvl[NLAY*DM*HHD];
__device__ bf16 twoh[NLAY*DM*HHD], twol[NLAY*DM*HHD];
__device__ bf16 twgsh[NLAY*FF*DM], twgsl[NLAY*FF*DM];
__device__ bf16 twush[NLAY*FF*DM], twusl[NLAY*FF*DM];
__device__ bf16 twdsh[NLAY*DM*FF], twdsl[NLAY*DM*FF];
__device__ bf16 twgeh[(size_t)NLAY*NEXP*FF*DM], twgel[(size_t)NLAY*NEXP*FF*DM];
__device__ bf16 twueh[(size_t)NLAY*NEXP*FF*DM], twuel[(size_t)NLAY*NEXP*FF*DM];
__device__ bf16 twdeh[(size_t)NLAY*NEXP*DM*FF], twdel[(size_t)NLAY*NEXP*DM*FF];

// ---- HMMA / cp.async helpers ----
__device__ __forceinline__ unsigned smem_u32(const void* p){
    unsigned a;
    asm("{ .reg .u64 t; cvta.to.shared.u64 t, %1; cvt.u32.u64 %0, t; }" : "=r"(a) : "l"(p));
    return a;
}
#define LDSM4(r, addr) \
    asm volatile("ldmatrix.sync.aligned.m8n8.x4.shared.b16 {%0,%1,%2,%3}, [%4];" \
        : "=r"((r)[0]), "=r"((r)[1]), "=r"((r)[2]), "=r"((r)[3]) : "r"(addr))
#define MMA16816(acc, a, b0v, b1v) \
    asm volatile("mma.sync.aligned.m16n8k16.row.col.f32.bf16.bf16.f32 " \
        "{%0,%1,%2,%3}, {%4,%5,%6,%7}, {%8,%9}, {%0,%1,%2,%3};" \
        : "+f"((acc)[0]), "+f"((acc)[1]), "+f"((acc)[2]), "+f"((acc)[3]) \
        : "r"((a)[0]), "r"((a)[1]), "r"((a)[2]), "r"((a)[3]), "r"(b0v), "r"(b1v))
#define CP16(dst, src)      asm volatile("cp.async.cg.shared.global [%0], [%1], 16;" :: "r"(dst), "l"(src))
#define CP16Z(dst, src, sz) asm volatile("cp.async.cg.shared.global [%0], [%1], 16, %2;" :: "r"(dst), "l"(src), "r"(sz))
#define CPCOMMIT() asm volatile("cp.async.commit_group;" ::: "memory")
#define CPWAIT1()  asm volatile("cp.async.wait_group 1;" ::: "memory")
#define CPWAIT0()  asm volatile("cp.async.wait_group 0;" ::: "memory")

#define STG_BYTES 40960
#define MMA_SMEM  (2*STG_BYTES)
#define QK_SMEM   (4*128*72*2)
#define PV_STG    (2*128*40*2 + 2*64*40*2)
#define PV_SMEM   (2*PV_STG)

// ---------------- small kernels ----------------

__global__ void k_ropetab(){
    int i = blockIdx.x*blockDim.x + threadIdx.x;
    if (i >= SQ*16) return;
    int j = i & 15, p = i >> 4;
    double ang = (double)p * pow(10000.0, -(double)j/16.0);
    g_cosT[i] = (float)cos(ang); g_sinT[i] = (float)sin(ang);
}

__global__ void k_embed(const int* __restrict__ ids, const float* __restrict__ emb){
    int t = blockIdx.x;
    const float* er = emb + (long)ids[t]*DM;
    for (int d = threadIdx.x; d < DM; d += 256){
        float vv = er[d];
        g_x[(long)t*4096+d] = vv; g_x[(long)t*4096+1024+d] = vv;
        g_x[(long)t*4096+2048+d] = vv; g_x[(long)t*4096+3072+d] = vv;
    }
}

__global__ void k_rmsinv(){
    int t = blockIdx.x;
    __shared__ float red[256];
    const float* xt = g_x + (long)t*4096;
    float ss = 0.f;
    for (int i = threadIdx.x; i < 4096; i += 256){ float vv = xt[i]; ss += vv*vv; }
    red[threadIdx.x] = ss; __syncthreads();
    for (int s = 128; s > 0; s >>= 1){ if (threadIdx.x < s) red[threadIdx.x] += red[threadIdx.x+s]; __syncthreads(); }
    if (threadIdx.x == 0) g_inv[t] = rsqrtf(red[0]/4096.f + 1e-6f);
}

__global__ void k_htrans(const float* __restrict__ src, float* __restrict__ dst, int nout){
    int i = blockIdx.x*blockDim.x + threadIdx.x;
    if (i >= 4096*nout) return;
    int r = i / nout, c = i % nout;
    dst[(long)c*4096 + r] = src[i];
}

template<int NOUT>
__global__ void __launch_bounds__(256) k_hcT(const float* __restrict__ Wt, const float* __restrict__ bb,
                                             float* __restrict__ raw){
    __shared__ float sx[16][129];
    __shared__ float sw[128][25];
    int t0 = blockIdx.x*16;
    int tid = threadIdx.x;
    int tt = tid & 15, jb = tid >> 4;
    float acc0 = 0.f, acc1 = 0.f;
    for (int k0 = 0; k0 < 4096; k0 += 128){
        for (int i = tid; i < 16*128; i += 256){
            int r = i>>7, c = i&127;
            sx[r][c] = g_x[(long)(t0+r)*4096 + k0 + c];
        }
        for (int i = tid; i < 128*NOUT; i += 256){
            int j = i>>7, kk = i&127;
            sw[kk][j] = Wt[(long)j*4096 + k0 + kk];
        }
        __syncthreads();
        #pragma unroll 8
        for (int kk = 0; kk < 128; kk++){
            float xv = sx[tt][kk];
            acc0 += xv*sw[kk][jb];
            if (NOUT > 16) acc1 += xv*sw[kk][jb+16];
        }
        __syncthreads();
    }
    float inv = g_inv[t0+tt];
    if (jb < NOUT)      raw[(long)(t0+tt)*NOUT + jb]      = inv*acc0 + bb[jb];
    if (NOUT > 16 && jb+16 < NOUT) raw[(long)(t0+tt)*NOUT + jb+16] = inv*acc1 + bb[jb+16];
}

__global__ void k_sink(){
    int t = blockIdx.x*blockDim.x + threadIdx.x;
    if (t >= SQ) return;
    const float* r = g_raw + (long)t*NCH;
    for (int n = 0; n < 4; n++){ g_pre[t*4+n] = 1.f + tanhf(r[n]); g_post[t*4+n] = 1.f + tanhf(r[4+n]); }
    float M[16]; float mx = -1e30f;
    #pragma unroll
    for (int i = 0; i < 16; i++){ float vv = r[8+i] + ((i%5==0)?1.f:0.f); M[i]=vv; if (vv>mx) mx=vv; }
    #pragma unroll
    for (int i = 0; i < 16; i++) M[i] = expf(M[i]-mx);
    for (int it = 0; it < 20; it++){
        #pragma unroll
        for (int n = 0; n < 4; n++){
            float s = M[n*4]+M[n*4+1]+M[n*4+2]+M[n*4+3] + 1e-6f;
            for (int m = 0; m < 4; m++) M[n*4+m] /= s;
        }
        #pragma unroll
        for (int m = 0; m < 4; m++){
            float s = M[m]+M[4+m]+M[8+m]+M[12+m] + 1e-6f;
            for (int n = 0; n < 4; n++) M[n*4+m] /= s;
        }
    }
    for (int i = 0; i < 16; i++) g_comb[t*16+i] = M[i];
}

__global__ void k_coll(const float* __restrict__ ln){
    int t = blockIdx.x;
    __shared__ float red[256];
    float p0=g_pre[t*4],p1=g_pre[t*4+1],p2=g_pre[t*4+2],p3=g_pre[t*4+3];
    const float* xt = g_x + (long)t*4096;
    float local[4]; float ss = 0.f;
    #pragma unroll
    for (int c = 0; c < 4; c++){
        int d = threadIdx.x + c*256;
        float vv = p0*xt[d]+p1*xt[1024+d]+p2*xt[2048+d]+p3*xt[3072+d];
        local[c]=vv; ss += vv*vv;
    }
    red[threadIdx.x]=ss; __syncthreads();
    for (int s = 128; s > 0; s >>= 1){ if (threadIdx.x < s) red[threadIdx.x]+=red[threadIdx.x+s]; __syncthreads(); }
    float inv = rsqrtf(red[0]/1024.f + 1e-6f);
    #pragma unroll
    for (int c = 0; c < 4; c++){
        int d = threadIdx.x + c*256;
        g_h[(long)t*DM+d] = local[c]*inv*ln[d];
    }
}

// rope + split q/k to bf16 hi/lo in one pass.
__global__ void k_rope_split(){
    int i = blockIdx.x*blockDim.x + threadIdx.x;
    if (i >= SQ*NHD*32) return;
    int j = i & 31, h = (i>>5)&15, s = i>>9;
    long base = (long)s*HHD + h*64;
    if (j < 16){
        float c = g_cosT[s*16+j], sn = g_sinT[s*16+j];
        float x1=g_q[base+j], x2=g_q[base+16+j];
        float q1 = x1*c-x2*sn, q2 = x1*sn+x2*c;
        bf16 h1 = __float2bfloat16(q1), h2 = __float2bfloat16(q2);
        g_qsh[base+j]=h1; g_qsl[base+j]=__float2bfloat16(q1-__bfloat162float(h1));
        g_qsh[base+16+j]=h2; g_qsl[base+16+j]=__float2bfloat16(q2-__bfloat162float(h2));
        x1=g_k[base+j]; x2=g_k[base+16+j];
        q1 = x1*c-x2*sn; q2 = x1*sn+x2*c;
        h1 = __float2bfloat16(q1); h2 = __float2bfloat16(q2);
        g_ksh[base+j]=h1; g_ksl[base+j]=__float2bfloat16(q1-__bfloat162float(h1));
        g_ksh[base+16+j]=h2; g_ksl[base+16+j]=__float2bfloat16(q2-__bfloat162float(h2));
    } else {
        int d1 = j + 16;   // 32..47
        int d2 = j + 32;   // 48..63
        float q = g_q[base+d1];
        bf16 hh = __float2bfloat16(q);
        g_qsh[base+d1]=hh; g_qsl[base+d1]=__float2bfloat16(q-__bfloat162float(hh));
        float kk = g_k[base+d1];
        hh = __float2bfloat16(kk);
        g_ksh[base+d1]=hh; g_ksl[base+d1]=__float2bfloat16(kk-__bfloat162float(hh));
        q = g_q[base+d2];
        hh = __float2bfloat16(q);
        g_qsh[base+d2]=hh; g_qsl[base+d2]=__float2bfloat16(q-__bfloat162float(hh));
        kk = g_k[base+d2];
        hh = __float2bfloat16(kk);
        g_ksh[base+d2]=hh; g_ksl[base+d2]=__float2bfloat16(kk-__bfloat162float(hh));
    }
}

// ---- HMMA scores: S[128q x 128k] per head, K=64, single stage ----
__global__ void __launch_bounds__(256) k_att_qk(){
    int h = blockIdx.z, q0 = blockIdx.y*128, k0 = blockIdx.x*128;
    if (k0 > q0 + 127) return;
    extern __shared__ char dsm[];
    bf16* sQh = (bf16*)dsm;
    bf16* sQl = sQh + 128*72;
    bf16* sKh = sQl + 128*72;
    bf16* sKl = sKh + 128*72;
    int tid = threadIdx.x, wid = tid>>5, lane = tid&31;
    int r = tid>>1, cb = (tid&1)*32;
    #pragma unroll
    for (int j = 0; j < 4; j++){
        long qoff = (long)(q0+r)*HHD + h*64 + cb + j*8;
        long koff = (long)(k0+r)*HHD + h*64 + cb + j*8;
        CP16(smem_u32(&sQh[r*72 + cb + j*8]), g_qsh + qoff);
        CP16(smem_u32(&sQl[r*72 + cb + j*8]), g_qsl + qoff);
        CP16(smem_u32(&sKh[r*72 + cb + j*8]), g_ksh + koff);
        CP16(smem_u32(&sKl[r*72 + cb + j*8]), g_ksl + koff);
    }
    CPCOMMIT(); CPWAIT0();
    __syncthreads();
    int wm = (wid&3)*32, wn = (wid>>2)*64;
    float acc[2][8][4] = {};
    int qd = lane>>3, lr = lane&7;
    int aRow = lr + (qd&1)*8, aCol = (qd>>1)*8;
    int bRow = lr + (qd>>1)*8, bCol = (qd&1)*8;
    #pragma unroll
    for (int ks = 0; ks < 64; ks += 16){
        unsigned aH[2][4], aL[2][4];
        #pragma unroll
        for (int mt = 0; mt < 2; mt++){
            LDSM4(aH[mt], smem_u32(&sQh[(wm + mt*16 + aRow)*72 + ks + aCol]));
            LDSM4(aL[mt], smem_u32(&sQl[(wm + mt*16 + aRow)*72 + ks + aCol]));
        }
        #pragma unroll
        for (int np = 0; np < 4; np++){
            unsigned bH[4], bL[4];
            LDSM4(bH, smem_u32(&sKh[(wn + np*16 + bRow)*72 + ks + bCol]));
            LDSM4(bL, smem_u32(&sKl[(wn + np*16 + bRow)*72 + ks + bCol]));
            #pragma unroll
            for (int mt = 0; mt < 2; mt++){
                MMA16816(acc[mt][np*2],   aH[mt], bH[0], bH[1]);
                MMA16816(acc[mt][np*2+1], aH[mt], bH[2], bH[3]);
                MMA16816(acc[mt][np*2],   aH[mt], bL[0], bL[1]);
                MMA16816(acc[mt][np*2+1], aH[mt], bL[2], bL[3]);
                MMA16816(acc[mt][np*2],   aL[mt], bH[0], bH[1]);
                MMA16816(acc[mt][np*2+1], aL[mt], bH[2], bH[3]);
            }
        }
    }
    float* out = g_scr + (size_t)h*SQ*SQ;
    #pragma unroll
    for (int mt = 0; mt < 2; mt++){
        size_t row = q0 + wm + mt*16 + (lane>>2);
        #pragma unroll
        for (int nt = 0; nt < 8; nt++){
            size_t col = k0 + wn + nt*8 + (lane&3)*2;
            *(float2*)&out[row*SQ + col]     = make_float2(acc[mt][nt][0]*0.125f, acc[mt][nt][1]*0.125f);
            *(float2*)&out[(row+8)*SQ + col] = make_float2(acc[mt][nt][2]*0.125f, acc[mt][nt][3]*0.125f);
        }
    }
}

// softmax: fp32 scores -> bf16 hi/lo P, zero-filled to 128-tile end
__global__ void k_softmax2(){
    int h = blockIdx.y, qi = blockIdx.x;
    float* row = g_scr + (size_t)h*SQ*SQ + (size_t)qi*SQ;
    bf16* oh = g_ph + (size_t)h*SQ*SQ + (size_t)qi*SQ;
    bf16* ol = g_pl + (size_t)h*SQ*SQ + (size_t)qi*SQ;
    int n = qi + 1;
    __shared__ float red[256];
    float mx = -1e30f;
    for (int i = threadIdx.x; i < n; i += 256) mx = fmaxf(mx, row[i]);
    red[threadIdx.x]=mx; __syncthreads();
    for (int s = 128; s > 0; s >>= 1){ if (threadIdx.x < s) red[threadIdx.x]=fmaxf(red[threadIdx.x],red[threadIdx.x+s]); __syncthreads(); }
    mx = red[0]; __syncthreads();
    float sum = 0.f;
    for (int i = threadIdx.x; i < n; i += 256){ float e = expf(row[i]-mx); row[i]=e; sum+=e; }
    red[threadIdx.x]=sum; __syncthreads();
    for (int s = 128; s > 0; s >>= 1){ if (threadIdx.x < s) red[threadIdx.x]+=red[threadIdx.x+s]; __syncthreads(); }
    float invs = 1.f/red[0];
    for (int i = threadIdx.x; i < n; i += 256){
        float p = row[i]*invs;
        bf16 hi = __float2bfloat16(p);
        oh[i] = hi;
        ol[i] = __float2bfloat16(p - __bfloat162float(hi));
    }
    int end = ((qi>>7)+1)<<7;
    bf16 z = __float2bfloat16(0.f);
    for (int i = n + threadIdx.x; i < end; i += 256){ oh[i] = z; ol[i] = z; }
}

// ---- HMMA PV: O[128q x 64d] per head; A=P, B=Vt[d][seq]; 2-stage pipeline ----
__global__ void __launch_bounds__(256) k_att_pv(){
    int q0 = blockIdx.x*128, h = blockIdx.y;
    extern __shared__ char dsm[];
    int tid = threadIdx.x, wid = tid>>5, lane = tid&31;
    int wm = wid*16;
    float acc[8][4] = {};
    int qd = lane>>3, lr = lane&7;
    int aRow = lr + (qd&1)*8, aCol = (qd>>1)*8;
    int bRow = lr + (qd>>1)*8, bCol = (qd&1)*8;
    int r0 = tid>>2, q0i = (tid&3)*8;
    int rb = tid>>2, cbv = (tid&3)*8;
    const bf16* Pbh = g_ph + (size_t)h*SQ*SQ;
    const bf16* Pbl = g_pl + (size_t)h*SQ*SQ;
    const bf16* Vbh = g_vth + (size_t)h*64*SQ;
    const bf16* Vbl = g_vtl + (size_t)h*64*SQ;

    #define PV_LOAD(s, kc) do { \
        bf16* _ph = (bf16*)(dsm + (s)*PV_STG); \
        bf16* _pl = (bf16*)(dsm + (s)*PV_STG + 10240); \
        bf16* _vh = (bf16*)(dsm + (s)*PV_STG + 20480); \
        bf16* _vl = (bf16*)(dsm + (s)*PV_STG + 25600); \
        CP16(smem_u32(&_ph[r0*40 + q0i]), Pbh + (size_t)(q0+r0)*SQ + (kc) + q0i); \
        CP16(smem_u32(&_ph[(r0+64)*40 + q0i]), Pbh + (size_t)(q0+r0+64)*SQ + (kc) + q0i); \
        CP16(smem_u32(&_pl[r0*40 + q0i]), Pbl + (size_t)(q0+r0)*SQ + (kc) + q0i); \
        CP16(smem_u32(&_pl[(r0+64)*40 + q0i]), Pbl + (size_t)(q0+r0+64)*SQ + (kc) + q0i); \
        CP16(smem_u32(&_vh[rb*40 + cbv]), Vbh + (size_t)rb*SQ + (kc) + cbv); \
        CP16(smem_u32(&_vl[rb*40 + cbv]), Vbl + (size_t)rb*SQ + (kc) + cbv); \
    } while(0)

    int nk = (q0 + 128) >> 5;
    PV_LOAD(0, 0);
    CPCOMMIT();
    for (int t = 0; t < nk; t++){
        int buf = t & 1;
        if (t+1 < nk){
            PV_LOAD(buf^1, (t+1)<<5);
            CPCOMMIT();
            CPWAIT1();
        } else {
            CPWAIT0();
        }
        __syncthreads();
        bf16* sPh = (bf16*)(dsm + buf*PV_STG);
        bf16* sPl = (bf16*)(dsm + buf*PV_STG + 10240);
        bf16* sVh = (bf16*)(dsm + buf*PV_STG + 20480);
        bf16* sVl = (bf16*)(dsm + buf*PV_STG + 25600);
        #pragma unroll
        for (int ks = 0; ks < 32; ks += 16){
            unsigned aH[4], aL[4];
            LDSM4(aH, smem_u32(&sPh[(wm + aRow)*40 + ks + aCol]));
            LDSM4(aL, smem_u32(&sPl[(wm + aRow)*40 + ks + aCol]));
            #pragma unroll
            for (int np = 0; np < 4; np++){
                unsigned bH[4], bL[4];
                LDSM4(bH, smem_u32(&sVh[(np*16 + bRow)*40 + ks + bCol]));
                LDSM4(bL, smem_u32(&sVl[(np*16 + bRow)*40 + ks + bCol]));
                MMA16816(acc[np*2],   aH, bH[0], bH[1]);
                MMA16816(acc[np*2+1], aH, bH[2], bH[3]);
                MMA16816(acc[np*2],   aH, bL[0], bL[1]);
                MMA16816(acc[np*2+1], aH, bL[2], bL[3]);
                MMA16816(acc[np*2],   aL, bH[0], bH[1]);
                MMA16816(acc[np*2+1], aL, bH[2], bH[3]);
            }
        }
        __syncthreads();
    }
    #undef PV_LOAD
    #pragma unroll
    for (int half = 0; half < 2; half++){
        long row = q0 + wm + half*8 + (lane>>2);
        #pragma unroll
        for (int nt = 0; nt < 8; nt++){
            long col = h*64 + nt*8 + (lane&3)*2;
            float v0 = acc[nt][half*2], v1 = acc[nt][half*2+1];
            bf16 h0 = __float2bfloat16(v0), h1 = __float2bfloat16(v1);
            g_aoh[row*HHD + col]   = h0;
            g_aol[row*HHD + col]   = __float2bfloat16(v0 - __bfloat162float(h0));
            g_aoh[row*HHD + col+1] = h1;
            g_aol[row*HHD + col+1] = __float2bfloat16(v1 - __bfloat162float(h1));
        }
    }
}

__global__ void k_combine(){
    int t = blockIdx.x;
    float ps[4], cb[16];
    #pragma unroll
    for (int n = 0; n < 4; n++) ps[n] = g_post[t*4+n];
    #pragma unroll
    for (int i = 0; i < 16; i++) cb[i] = g_comb[t*16+i];
    for (int d = threadIdx.x; d < DM; d += 256){
        float xv[4];
        #pragma unroll
        for (int n = 0; n < 4; n++) xv[n] = g_x[(long)t*4096 + n*1024 + d];
        float av = g_a[(long)t*DM + d];
        #pragma unroll
        for (int m = 0; m < 4; m++){
            float s = ps[m]*av;
            #pragma unroll
            for (int n = 0; n < 4; n++) s += cb[n*4+m]*xv[n];
            g_x[(long)t*4096 + m*1024 + d] = s;
        }
    }
}

__global__ void k_reset(){
    int i = blockIdx.x*blockDim.x + threadIdx.x;
    if (i < NEXP){ g_cnt[i]=0; g_fill[i]=0; }
    if (i < MAXENT) g_etok[i] = -1;
}

__global__ void k_gate(const float* __restrict__ gw, const int* __restrict__ ids,
                       const int* __restrict__ t2e, int layer){
    int t = blockIdx.x;
    __shared__ float sm[256][8];
    __shared__ float sc[8];
    float acc[8] = {};
    const float* xt = g_h + (long)t*DM;
    for (int i = threadIdx.x; i < DM; i += 256){
        float vv = xt[i];
        #pragma unroll
        for (int e = 0; e < 8; e++) acc[e] += vv*gw[e*DM+i];
    }
    #pragma unroll
    for (int e = 0; e < 8; e++) sm[threadIdx.x][e] = acc[e];
    __syncthreads();
    if (threadIdx.x < 8){
        float s = 0.f;
        for (int r = 0; r < 256; r++) s += sm[r][threadIdx.x];
        float sp = (s > 20.f) ? s : log1pf(expf(s));
        sc[threadIdx.x] = sqrtf(sp);
    }
    __syncthreads();
    if (threadIdx.x == 0){
        int i0, i1;
        if (layer < 1){ int id = ids[t]; i0 = t2e[id*2]; i1 = t2e[id*2+1]; }
        else {
            i0 = 0;
            for (int e = 1; e < 8; e++) if (sc[e] > sc[i0]) i0 = e;
            i1 = -1; float best = -1e30f;
            for (int e = 0; e < 8; e++){ if (e==i0) continue; if (sc[e] > best){ best = sc[e]; i1 = e; } }
        }
        float w0 = sc[i0], w1 = sc[i1];
        float sw = w0 + w1 + 1e-20f;
        g_ew[t*2] = w0/sw*2.5f; g_ew[t*2+1] = w1/sw*2.5f;
        g_eidx[t*2] = i0; g_eidx[t*2+1] = i1;
        atomicAdd(&g_cnt[i0], 1); atomicAdd(&g_cnt[i1], 1);
    }
}

__global__ void k_off(){
    if (threadIdx.x == 0){
        int o = 0;
        for (int e = 0; e < NEXP; e++){ g_off[e] = o; o += ((g_cnt[e]+127)/128)*128; }
        g_off[NEXP] = o;
    }
}

__global__ void k_scatter(){
    int i = blockIdx.x*blockDim.x + threadIdx.x;
    if (i >= SQ*KSEL) return;
    int e = g_eidx[i];
    int pos = g_off[e] + atomicAdd(&g_fill[e], 1);
    g_etok[pos] = i >> 1;
    g_eof[i] = pos;
}

__global__ void k_silu_split(const float* __restrict__ g, const float* __restrict__ u,
                             bf16* __restrict__ oh, bf16* __restrict__ ol, int n){
    int i = blockIdx.x*blockDim.x + threadIdx.x;
    if (i >= n) return;
    float x = g[i];
    float s = (x / (1.f + expf(-x))) * u[i];
    bf16 hi = __float2bfloat16(s);
    oh[i] = hi;
    ol[i] = __float2bfloat16(s - __bfloat162float(hi));
}

__global__ void k_split(const float* __restrict__ src, bf16* __restrict__ oh, bf16* __restrict__ ol, int n){
    int i = blockIdx.x*blockDim.x + threadIdx.x;
    if (i >= n) return;
    float x = src[i];
    bf16 hi = __float2bfloat16(x);
    oh[i] = hi;
    ol[i] = __float2bfloat16(x - __bfloat162float(hi));
}

// transpose + split with vectorized bf16x2 stores:
// src [K][N] fp32 (+z*K*N) -> dst [N][K] bf16 hi/lo
__global__ void k_tsplit(const float* __restrict__ src, bf16* __restrict__ dh, bf16* __restrict__ dl,
                         int K, int N){
    long zo = (long)blockIdx.z * K * N;
    src += zo; dh += zo; dl += zo;
    __shared__ float t[32][33];
    int n0 = blockIdx.x*32, k0 = blockIdx.y*32;
    int tx = threadIdx.x, ty = threadIdx.y;
    #pragma unroll
    for (int j = 0; j < 4; j++)
        t[ty + j*8][tx] = src[(long)(k0 + ty + j*8)*N + n0 + tx];   // t[k][n]
    __syncthreads();
    int k2 = (tx & 15)*2, half = tx >> 4;
    #pragma unroll
    for (int j = 0; j < 2; j++){
        int nn = ty + j*8 + half*16;
        float f0 = t[k2][nn],   f1 = t[k2+1][nn];
        bf16 h0 = __float2bfloat16(f0), h1 = __float2bfloat16(f1);
        bf16 l0 = __float2bfloat16(f0 - __bfloat162float(h0));
        bf16 l1 = __float2bfloat16(f1 - __bfloat162float(h1));
        long o = (long)(n0 + nn)*K + k0 + k2;
        __nv_bfloat162 hv; hv.x = h0; hv.y = h1;
        __nv_bfloat162 lv; lv.x = l0; lv.y = l1;
        *(__nv_bfloat162*)&dh[o] = hv;
        *(__nv_bfloat162*)&dl[o] = lv;
    }
}

__global__ void k_routedadd(){
    int t = blockIdx.x;
    int e0 = g_eof[t*2], e1 = g_eof[t*2+1];
    float w0 = g_ew[t*2], w1 = g_ew[t*2+1];
    for (int d = threadIdx.x; d < DM; d += 256)
        g_a[(long)t*DM+d] += w0*g_ed[(long)e0*DM+d] + w1*g_ed[(long)e1*DM+d];
}

__global__ void k_final(const float* __restrict__ fw){
    int t = blockIdx.x;
    __shared__ float red[256];
    float p[4];
    #pragma unroll
    for (int n = 0; n < 4; n++) p[n] = 1.f + tanhf(g_raw[t*4+n]);
    const float* xt = g_x + (long)t*4096;
    float local[4]; float ss = 0.f;
    #pragma unroll
    for (int c = 0; c < 4; c++){
        int d = threadIdx.x + c*256;
        float vv = p[0]*xt[d]+p[1]*xt[1024+d]+p[2]*xt[2048+d]+p[3]*xt[3072+d];
        local[c]=vv; ss += vv*vv;
    }
    red[threadIdx.x]=ss; __syncthreads();
    for (int s = 128; s > 0; s >>= 1){ if (threadIdx.x < s) red[threadIdx.x]+=red[threadIdx.x+s]; __syncthreads(); }
    float inv = rsqrtf(red[0]/1024.f + 1e-6f);
    #pragma unroll
    for (int c = 0; c < 4; c++){
        int d = threadIdx.x + c*256;
        g_h[(long)t*DM+d] = local[c]*inv*fw[d];
    }
}

// ---------------- pipelined HMMA GEMM: C[M,N] = A[M,K] x B[N,K]^T ----------------
// Grouped CTA rasterization (group_m=8, n-fastest within group) for L2 reuse of B.
// Requires gridDim.y % 8 == 0 (all call sites use 16).
__global__ void __launch_bounds__(256) k_mma(const bf16* __restrict__ Ah, const bf16* __restrict__ Al,
                                             const bf16* __restrict__ Bh, const bf16* __restrict__ Bl,
                                             float* __restrict__ C, int N, int K){
    extern __shared__ char dsm[];
    int tid = threadIdx.x, wid = tid>>5, lane = tid&31;
    int nT = gridDim.x;
    int bid = blockIdx.y*nT + blockIdx.x;
    int grp = bid / (8*nT), rem = bid % (8*nT);
    int m0 = (grp*8 + (rem & 7))*128;
    int n0 = (rem >> 3)*128;
    int wm = (wid&3)*32, wn = (wid>>2)*64;
    float acc[2][8][4] = {};
    int qd = lane>>3, lr = lane&7;
    int aRow = lr + (qd&1)*8, aCol = (qd>>1)*8;
    int bRow = lr + (qd>>1)*8, bCol = (qd&1)*8;
    int r0 = tid>>2, q0i = (tid&3)*8;
    int r1 = r0 + 64;

    #define LOAD_STAGE(s, kc) do { \
        bf16* _ah = (bf16*)(dsm + (s)*STG_BYTES); \
        bf16* _al = (bf16*)(dsm + (s)*STG_BYTES + 10240); \
        bf16* _bh = (bf16*)(dsm + (s)*STG_BYTES + 20480); \
        bf16* _bl = (bf16*)(dsm + (s)*STG_BYTES + 30720); \
        CP16(smem_u32(&_ah[r0*40 + q0i]), Ah + (long)(m0+r0)*K + (kc) + q0i); \
        CP16(smem_u32(&_ah[r1*40 + q0i]), Ah + (long)(m0+r1)*K + (kc) + q0i); \
        CP16(smem_u32(&_al[r0*40 + q0i]), Al + (long)(m0+r0)*K + (kc) + q0i); \
        CP16(smem_u32(&_al[r1*40 + q0i]), Al + (long)(m0+r1)*K + (kc) + q0i); \
        CP16(smem_u32(&_bh[r0*40 + q0i]), Bh + (long)(n0+r0)*K + (kc) + q0i); \
        CP16(smem_u32(&_bh[r1*40 + q0i]), Bh + (long)(n0+r1)*K + (kc) + q0i); \
        CP16(smem_u32(&_bl[r0*40 + q0i]), Bl + (long)(n0+r0)*K + (kc) + q0i); \
        CP16(smem_u32(&_bl[r1*40 + q0i]), Bl + (long)(n0+r1)*K + (kc) + q0i); \
    } while(0)

    LOAD_STAGE(0, 0);
    CPCOMMIT();
    int nk = K >> 5;
    for (int t = 0; t < nk; t++){
        int buf = t & 1;
        if (t+1 < nk){
            LOAD_STAGE(buf^1, (t+1)<<5);
            CPCOMMIT();
            CPWAIT1();
        } else {
            CPWAIT0();
        }
        __syncthreads();
        bf16* sAh = (bf16*)(dsm + buf*STG_BYTES);
        bf16* sAl = (bf16*)(dsm + buf*STG_BYTES + 10240);
        bf16* sBh = (bf16*)(dsm + buf*STG_BYTES + 20480);
        bf16* sBl = (bf16*)(dsm + buf*STG_BYTES + 30720);
        #pragma unroll
        for (int ks = 0; ks < 32; ks += 16){
            unsigned aH[2][4], aL[2][4];
            #pragma unroll
            for (int mt = 0; mt < 2; mt++){
                LDSM4(aH[mt], smem_u32(&sAh[(wm + mt*16 + aRow)*40 + ks + aCol]));
                LDSM4(aL[mt], smem_u32(&sAl[(wm + mt*16 + aRow)*40 + ks + aCol]));
            }
            #pragma unroll
            for (int np = 0; np < 4; np++){
                unsigned bH[4], bL[4];
                LDSM4(bH, smem_u32(&sBh[(wn + np*16 + bRow)*40 + ks + bCol]));
                LDSM4(bL, smem_u32(&sBl[(wn + np*16 + bRow)*40 + ks + bCol]));
                #pragma unroll
                for (int mt = 0; mt < 2; mt++){
                    MMA16816(acc[mt][np*2],   aH[mt], bH[0], bH[1]);
                    MMA16816(acc[mt][np*2+1], aH[mt], bH[2], bH[3]);
                    MMA16816(acc[mt][np*2],   aH[mt], bL[0], bL[1]);
                    MMA16816(acc[mt][np*2+1], aH[mt], bL[2], bL[3]);
                    MMA16816(acc[mt][np*2],   aL[mt], bH[0], bH[1]);
                    MMA16816(acc[mt][np*2+1], aL[mt], bH[2], bH[3]);
                }
            }
        }
        __syncthreads();
    }
    #undef LOAD_STAGE
    #pragma unroll
    for (int mt = 0; mt < 2; mt++){
        long row = m0 + wm + mt*16 + (lane>>2);
        #pragma unroll
        for (int nt = 0; nt < 8; nt++){
            long col = n0 + wn + nt*8 + (lane&3)*2;
            *(float2*)&C[row*N + col]     = make_float2(acc[mt][nt][0], acc[mt][nt][1]);
            *(float2*)&C[(row+8)*N + col] = make_float2(acc[mt][nt][2], acc[mt][nt][3]);
        }
    }
}

// pipelined segmented (per-expert) HMMA GEMM with optional token gather on A
__global__ void __launch_bounds__(256) k_mma_seg(const bf16* __restrict__ Ah, const bf16* __restrict__ Al,
                                                 const bf16* __restrict__ Bh0, const bf16* __restrict__ Bl0,
                                                 float* __restrict__ C, int N, int K, long Bstride, int useGather){
    int e = blockIdx.z;
    int seg0 = g_off[e], nrows = g_cnt[e];
    int m0 = blockIdx.y*128;
    if (m0 >= nrows) return;
    int n0 = blockIdx.x*128;
    const bf16* Bh = Bh0 + (long)e*Bstride;
    const bf16* Bl = Bl0 + (long)e*Bstride;
    extern __shared__ char dsm[];
    int tid = threadIdx.x, wid = tid>>5, lane = tid&31;
    int wm = (wid&3)*32, wn = (wid>>2)*64;
    float acc[2][8][4] = {};
    int qd = lane>>3, lr = lane&7;
    int aRow = lr + (qd&1)*8, aCol = (qd>>1)*8;
    int bRow = lr + (qd>>1)*8, bCol = (qd&1)*8;
    int r0 = tid>>2, q0i = (tid&3)*8;
    int r1 = r0 + 64;
    const bf16 *a0h, *a0l, *a1h, *a1l;
    unsigned sz0 = 16, sz1 = 16;
    {
        int ge0 = seg0 + m0 + r0, ge1 = seg0 + m0 + r1;
        if (useGather){
            int tk0 = g_etok[ge0], tk1 = g_etok[ge1];
            if (tk0 >= 0){ a0h = Ah + (long)tk0*K; a0l = Al + (long)tk0*K; } else { a0h = Ah; a0l = Al; sz0 = 0; }
            if (tk1 >= 0){ a1h = Ah + (long)tk1*K; a1l = Al + (long)tk1*K; } else { a1h = Ah; a1l = Al; sz1 = 0; }
        } else {
            a0h = Ah + (long)ge0*K; a0l = Al + (long)ge0*K;
            a1h = Ah + (long)ge1*K; a1l = Al + (long)ge1*K;
        }
    }

    #define LOAD_STAGE_S(s, kc) do { \
        bf16* _ah = (bf16*)(dsm + (s)*STG_BYTES); \
        bf16* _al = (bf16*)(dsm + (s)*STG_BYTES + 10240); \
        bf16* _bh = (bf16*)(dsm + (s)*STG_BYTES + 20480); \
        bf16* _bl = (bf16*)(dsm + (s)*STG_BYTES + 30720); \
        CP16Z(smem_u32(&_ah[r0*40 + q0i]), a0h + (kc) + q0i, sz0); \
        CP16Z(smem_u32(&_ah[r1*40 + q0i]), a1h + (kc) + q0i, sz1); \
        CP16Z(smem_u32(&_al[r0*40 + q0i]), a0l + (kc) + q0i, sz0); \
        CP16Z(smem_u32(&_al[r1*40 + q0i]), a1l + (kc) + q0i, sz1); \
        CP16(smem_u32(&_bh[r0*40 + q0i]), Bh + (long)(n0+r0)*K + (kc) + q0i); \
        CP16(smem_u32(&_bh[r1*40 + q0i]), Bh + (long)(n0+r1)*K + (kc) + q0i); \
        CP16(smem_u32(&_bl[r0*40 + q0i]), Bl + (long)(n0+r0)*K + (kc) + q0i); \
        CP16(smem_u32(&_bl[r1*40 + q0i]), Bl + (long)(n0+r1)*K + (kc) + q0i); \
    } while(0)

    LOAD_STAGE_S(0, 0);
    CPCOMMIT();
    int nk = K >> 5;
    for (int t = 0; t < nk; t++){
        int buf = t & 1;
        if (t+1 < nk){
            LOAD_STAGE_S(buf^1, (t+1)<<5);
            CPCOMMIT();
            CPWAIT1();
        } else {
            CPWAIT0();
        }
        __syncthreads();
        bf16* sAh = (bf16*)(dsm + buf*STG_BYTES);
        bf16* sAl = (bf16*)(dsm + buf*STG_BYTES + 10240);
        bf16* sBh = (bf16*)(dsm + buf*STG_BYTES + 20480);
        bf16* sBl = (bf16*)(dsm + buf*STG_BYTES + 30720);
        #pragma unroll
        for (int ks = 0; ks < 32; ks += 16){
            unsigned aH[2][4], aL[2][4];
            #pragma unroll
            for (int mt = 0; mt < 2; mt++){
                LDSM4(aH[mt], smem_u32(&sAh[(wm + mt*16 + aRow)*40 + ks + aCol]));
                LDSM4(aL[mt], smem_u32(&sAl[(wm + mt*16 + aRow)*40 + ks + aCol]));
            }
            #pragma unroll
            for (int np = 0; np < 4; np++){
                unsigned bH[4], bL[4];
                LDSM4(bH, smem_u32(&sBh[(wn + np*16 + bRow)*40 + ks + bCol]));
                LDSM4(bL, smem_u32(&sBl[(wn + np*16 + bRow)*40 + ks + bCol]));
                #pragma unroll
                for (int mt = 0; mt < 2; mt++){
                    MMA16816(acc[mt][np*2],   aH[mt], bH[0], bH[1]);
                    MMA16816(acc[mt][np*2+1], aH[mt], bH[2], bH[3]);
                    MMA16816(acc[mt][np*2],   aH[mt], bL[0], bL[1]);
                    MMA16816(acc[mt][np*2+1], aH[mt], bL[2], bL[3]);
                    MMA16816(acc[mt][np*2],   aL[mt], bH[0], bH[1]);
                    MMA16816(acc[mt][np*2+1], aL[mt], bH[2], bH[3]);
                }
            }
        }
        __syncthreads();
    }
    #undef LOAD_STAGE_S
    #pragma unroll
    for (int mt = 0; mt < 2; mt++){
        long row = seg0 + m0 + wm + mt*16 + (lane>>2);
        #pragma unroll
        for (int nt = 0; nt < 8; nt++){
            long col = n0 + wn + nt*8 + (lane&3)*2;
            *(float2*)&C[row*N + col]     = make_float2(acc[mt][nt][0], acc[mt][nt][1]);
            *(float2*)&C[(row+8)*N + col] = make_float2(acc[mt][nt][2], acc[mt][nt][3]);
        }
    }
}

static float* SYM(const void* symbol){
    void* p = nullptr;
    cudaGetSymbolAddress(&p, symbol);
    return (float*)p;
}

extern "C" void kernel_launch(void* const* d_in, const int* in_sizes, int n_in,
                              void* d_out, int out_size){
    const int*   ids    = (const int*)d_in[0];
    const int*   t2e    = (const int*)d_in[1];
    const float* embed  = (const float*)d_in[2];
    const float* ahw    = (const float*)d_in[3];
    const float* ahb    = (const float*)d_in[4];
    const float* fhw    = (const float*)d_in[5];
    const float* fhb    = (const float*)d_in[6];
    const float* ln1    = (const float*)d_in[7];
    const float* ln2    = (const float*)d_in[8];
    const float* wq     = (const float*)d_in[9];
    const float* wk     = (const float*)d_in[10];
    const float* wv     = (const float*)d_in[11];
    const float* wo     = (const float*)d_in[12];
    const float* gatew  = (const float*)d_in[13];
    const float* wge    = (const float*)d_in[14];
    const float* wue    = (const float*)d_in[15];
    const float* wde    = (const float*)d_in[16];
    const float* wgs    = (const float*)d_in[17];
    const float* wus    = (const float*)d_in[18];
    const float* wds    = (const float*)d_in[19];
    const float* headw  = (const float*)d_in[20];
    const float* headb  = (const float*)d_in[21];
    const float* fnw    = (const float*)d_in[22];
    const float* lmh    = (const float*)d_in[23];
    float* out = (float*)d_out;

    float* ph   = SYM(g_h);
    float* pq   = SYM(g_q);
    float* pk   = SYM(g_k);
    float* pv   = SYM(g_v);
    float* pa   = SYM(g_a);
    float* peg  = SYM(g_eg);
    float* peu  = SYM(g_eu);
    float* ped  = SYM(g_ed);
    float* ps1  = SYM(g_s1);
    float* ps2  = SYM(g_s2);
    float* praw = SYM(g_raw);
    float* ptah = SYM(t_ahw);
    float* ptfh = SYM(t_fhw);
    float* pthw = SYM(t_hw);
    bf16* pah  = (bf16*)SYM(g_ah);   bf16* pal  = (bf16*)SYM(g_al);
    bf16* paoh = (bf16*)SYM(g_aoh);  bf16* paol = (bf16*)SYM(g_aol);
    bf16* ps1h = (bf16*)SYM(g_s1h);  bf16* ps1l = (bf16*)SYM(g_s1l);
    bf16* pegh = (bf16*)SYM(g_egh);  bf16* pegl = (bf16*)SYM(g_egl);
    bf16* pvth = (bf16*)SYM(g_vth);  bf16* pvtl = (bf16*)SYM(g_vtl);
    bf16* pbh  = (bf16*)SYM(g_bh);   bf16* pbl  = (bf16*)SYM(g_bl);
    bf16* pqh  = (bf16*)SYM(twqh);   bf16* pql  = (bf16*)SYM(twql);
    bf16* pkh  = (bf16*)SYM(twkh);   bf16* pkl  = (bf16*)SYM(twkl);
    bf16* pvh  = (bf16*)SYM(twvh);   bf16* pvl  = (bf16*)SYM(twvl);
    bf16* poh  = (bf16*)SYM(twoh);   bf16* pol  = (bf16*)SYM(twol);
    bf16* pgsh = (bf16*)SYM(twgsh);  bf16* pgsl = (bf16*)SYM(twgsl);
    bf16* push = (bf16*)SYM(twush);  bf16* pusl = (bf16*)SYM(twusl);
    bf16* pdsh = (bf16*)SYM(twdsh);  bf16* pdsl = (bf16*)SYM(twdsl);
    bf16* pgeh = (bf16*)SYM(twgeh);  bf16* pgel = (bf16*)SYM(twgel);
    bf16* pueh = (bf16*)SYM(twueh);  bf16* puel = (bf16*)SYM(twuel);
    bf16* pdeh = (bf16*)SYM(twdeh);  bf16* pdel = (bf16*)SYM(twdel);

    cudaFuncSetAttribute(k_mma,     cudaFuncAttributeMaxDynamicSharedMemorySize, MMA_SMEM);
    cudaFuncSetAttribute(k_mma_seg, cudaFuncAttributeMaxDynamicSharedMemorySize, MMA_SMEM);
    cudaFuncSetAttribute(k_att_qk,  cudaFuncAttributeMaxDynamicSharedMemorySize, QK_SMEM);
    cudaFuncSetAttribute(k_att_pv,  cudaFuncAttributeMaxDynamicSharedMemorySize, PV_SMEM);

    dim3 tb(32,8);
    // ---- weight prep ----
    k_tsplit<<<dim3(VOC/32, DM/32), tb>>>(lmh, pbh, pbl, DM, VOC);
    for (int l = 0; l < NLAY; l++){
        long o1 = (long)l*DM*HHD, oS = (long)l*FF*DM, oE = (long)l*NEXP*FF*DM;
        k_tsplit<<<dim3(32,32), tb>>>(wq + o1, pqh + o1, pql + o1, DM, HHD);
        k_tsplit<<<dim3(32,32), tb>>>(wk + o1, pkh + o1, pkl + o1, DM, HHD);
        k_tsplit<<<dim3(32,32), tb>>>(wv + o1, pvh + o1, pvl + o1, DM, HHD);
        k_tsplit<<<dim3(32,32), tb>>>(wo + o1, poh + o1, pol + o1, HHD, DM);
        k_tsplit<<<dim3(16,32), tb>>>(wgs + oS, pgsh + oS, pgsl + oS, DM, FF);
        k_tsplit<<<dim3(16,32), tb>>>(wus + oS, push + oS, pusl + oS, DM, FF);
        k_tsplit<<<dim3(32,16), tb>>>(wds + oS, pdsh + oS, pdsl + oS, FF, DM);
        k_tsplit<<<dim3(16,32,8), tb>>>(wge + oE, pgeh + oE, pgel + oE, DM, FF);
        k_tsplit<<<dim3(16,32,8), tb>>>(wue + oE, pueh + oE, puel + oE, DM, FF);
        k_tsplit<<<dim3(32,16,8), tb>>>(wde + oE, pdeh + oE, pdel + oE, FF, DM);
        k_htrans<<<(4096*NCH+255)/256, 256>>>(ahw + (long)l*4096*NCH, ptah + (long)l*NCH*4096, NCH);
        k_htrans<<<(4096*NCH+255)/256, 256>>>(fhw + (long)l*4096*NCH, ptfh + (long)l*NCH*4096, NCH);
    }
    k_htrans<<<(4096*4+255)/256, 256>>>(headw, pthw, 4);

    k_ropetab<<<(SQ*16+255)/256, 256>>>();
    k_embed<<<SQ, 256>>>(ids, embed);

    dim3 gm_1024(8, 16);
    dim3 gm_512 (4, 16);
    dim3 gms_ff (4, MAXENT/128, 8);
    dim3 gms_dm (8, MAXENT/128, 8);
    dim3 gqk(16, 16, 16);
    dim3 gsm(SQ, 16);
    dim3 gpv(16, 16);

    for (int l = 0; l < NLAY; l++){
        long o1 = (long)l*DM*HHD, oS = (long)l*FF*DM, oE = (long)l*NEXP*FF*DM;
        // attention block
        k_rmsinv<<<SQ, 256>>>();
        k_hcT<NCH><<<SQ/16, 256>>>(ptah + (long)l*NCH*4096, ahb + l*NCH, praw);
        k_sink<<<(SQ+255)/256, 256>>>();
        k_coll<<<SQ, 256>>>(ln1 + l*DM);
        k_split<<<(SQ*DM+255)/256, 256>>>(ph, pah, pal, SQ*DM);
        k_mma<<<gm_1024, 256, MMA_SMEM>>>(pah, pal, pqh + o1, pql + o1, pq, HHD, DM);
        k_mma<<<gm_1024, 256, MMA_SMEM>>>(pah, pal, pkh + o1, pkl + o1, pk, HHD, DM);
        k_mma<<<gm_1024, 256, MMA_SMEM>>>(pah, pal, pvh + o1, pvl + o1, pv, HHD, DM);
        k_rope_split<<<(SQ*NHD*32+255)/256, 256>>>();
        k_tsplit<<<dim3(HHD/32, SQ/32), tb>>>(pv, pvth, pvtl, SQ, HHD);
        k_att_qk<<<gqk, 256, QK_SMEM>>>();
        k_softmax2<<<gsm, 256>>>();
        k_att_pv<<<gpv, 256, PV_SMEM>>>();
        k_mma<<<gm_1024, 256, MMA_SMEM>>>(paoh, paol, poh + o1, pol + o1, pa, DM, HHD);
        k_combine<<<SQ, 256>>>();
        // ffn block
        k_rmsinv<<<SQ, 256>>>();
        k_hcT<NCH><<<SQ/16, 256>>>(ptfh + (long)l*NCH*4096, fhb + l*NCH, praw);
        k_sink<<<(SQ+255)/256, 256>>>();
        k_coll<<<SQ, 256>>>(ln2 + l*DM);
        k_split<<<(SQ*DM+255)/256, 256>>>(ph, pah, pal, SQ*DM);
        k_reset<<<(MAXENT+255)/256, 256>>>();
        k_gate<<<SQ, 256>>>(gatew + (long)l*NEXP*DM, ids, t2e, l);
        k_off<<<1, 32>>>();
        k_scatter<<<(SQ*KSEL+255)/256, 256>>>();
        k_mma_seg<<<gms_ff, 256, MMA_SMEM>>>(pah, pal, pgeh + oE, pgel + oE, peg, FF, DM, (long)FF*DM, 1);
        k_mma_seg<<<gms_ff, 256, MMA_SMEM>>>(pah, pal, pueh + oE, puel + oE, peu, FF, DM, (long)FF*DM, 1);
        k_silu_split<<<((long)MAXENT*FF+255)/256, 256>>>(peg, peu, pegh, pegl, MAXENT*FF);
        k_mma_seg<<<gms_dm, 256, MMA_SMEM>>>(pegh, pegl, pdeh + oE, pdel + oE, ped, DM, FF, (long)DM*FF, 0);
        k_mma<<<gm_512, 256, MMA_SMEM>>>(pah, pal, pgsh + oS, pgsl + oS, ps1, FF, DM);
        k_mma<<<gm_512, 256, MMA_SMEM>>>(pah, pal, push + oS, pusl + oS, ps2, FF, DM);
        k_silu_split<<<(SQ*FF+255)/256, 256>>>(ps1, ps2, ps1h, ps1l, SQ*FF);
        k_mma<<<gm_1024, 256, MMA_SMEM>>>(ps1h, ps1l, pdsh + oS, pdsl + oS, pa, DM, FF);
        k_routedadd<<<SQ, 256>>>();
        k_combine<<<SQ, 256>>>();
    }

    // final head + lm head
    k_rmsinv<<<SQ, 256>>>();
    k_hcT<4><<<SQ/16, 256>>>(pthw, headb, praw);
    k_final<<<SQ, 256>>>(fnw);
    k_split<<<(SQ*DM+255)/256, 256>>>(ph, pah, pal, SQ*DM);
    dim3 glm(VOC/128, SQ/128);
    k_mma<<<glm, 256, MMA_SMEM>>>(pah, pal, pbh, pbl, out, VOC, DM);
}

// round 16
// speedup vs baseline: 1.0951x; 1.0951x over previous
#include <cuda_runtime.h>
#include <cuda_bf16.h>
#include <math.h>

#define SQ 2048
#define DM 1024
#define NS 4
#define NCH 24
#define NLAY 2
#define NHD 16
#define HHD 1024
#define NEXP 8
#define KSEL 2
#define FF 512
#define VOC 32000
#define MAXENT (SQ*KSEL + NEXP*128)
#define SCRN (16ULL*2048ULL*2048ULL)

typedef unsigned long long ull;
typedef __nv_bfloat16 bf16;

__device__ float g_x[SQ*NS*DM];
__device__ float g_raw[SQ*NCH];
__device__ float g_pre[SQ*NS];
__device__ float g_post[SQ*NS];
__device__ float g_comb[SQ*NS*NS];
__device__ float g_h[SQ*DM];
__device__ float g_q[SQ*HHD];
__device__ float g_k[SQ*HHD];
__device__ float g_v[SQ*HHD];
__device__ float g_scr[SCRN];
__device__ float g_a[SQ*DM];
__device__ float g_cosT[SQ*16];
__device__ float g_sinT[SQ*16];
__device__ int   g_eidx[SQ*KSEL];
__device__ float g_ew[SQ*KSEL];
__device__ int   g_cnt[NEXP];
__device__ int   g_off[NEXP+1];
__device__ int   g_fill[NEXP];
__device__ int   g_etok[MAXENT];
__device__ int   g_eof[SQ*KSEL];
__device__ float g_eg[(size_t)MAXENT*FF];
__device__ float g_eu[(size_t)MAXENT*FF];
__device__ float g_ed[(size_t)MAXENT*DM];
__device__ float g_s1[SQ*FF];
__device__ float g_s2[SQ*FF];
__device__ float t_ahw[NLAY*NCH*4096];
__device__ float t_fhw[NLAY*NCH*4096];
__device__ float t_hw[4*4096];
__device__ bf16 g_ah[SQ*DM],  g_al[SQ*DM];
__device__ bf16 g_aoh[SQ*HHD], g_aol[SQ*HHD];
__device__ bf16 g_s1h[SQ*FF],  g_s1l[SQ*FF];
__device__ bf16 g_egh[(size_t)MAXENT*FF], g_egl[(size_t)MAXENT*FF];
// attention bf16 operands
__device__ bf16 g_qsh[SQ*HHD], g_qsl[SQ*HHD];
__device__ bf16 g_ksh[SQ*HHD], g_ksl[SQ*HHD];
__device__ bf16 g_vth[HHD*SQ], g_vtl[HHD*SQ];
__device__ bf16 g_ph[SCRN], g_pl[SCRN];
__device__ bf16 g_bh[(size_t)VOC*DM], g_bl[(size_t)VOC*DM];
__device__ bf16 twqh[NLAY*DM*HHD], twql[NLAY*DM*HHD];
__device__ bf16 twkh[NLAY*DM*HHD], twkl[NLAY*DM*HHD];
__device__ bf16 twvh[NLAY*DM*HHD], twvl[NLAY*DM*HHD];
__device__ bf16 twoh[NLAY*DM*HHD], twol[NLAY*DM*HHD];
__device__ bf16 twgsh[NLAY*FF*DM], twgsl[NLAY*FF*DM];
__device__ bf16 twush[NLAY*FF*DM], twusl[NLAY*FF*DM];
__device__ bf16 twdsh[NLAY*DM*FF], twdsl[NLAY*DM*FF];
__device__ bf16 twgeh[(size_t)NLAY*NEXP*FF*DM], twgel[(size_t)NLAY*NEXP*FF*DM];
__device__ bf16 twueh[(size_t)NLAY*NEXP*FF*DM], twuel[(size_t)NLAY*NEXP*FF*DM];
__device__ bf16 twdeh[(size_t)NLAY*NEXP*DM*FF], twdel[(size_t)NLAY*NEXP*DM*FF];

// ---- HMMA / cp.async helpers ----
__device__ __forceinline__ unsigned smem_u32(const void* p){
    unsigned a;
    asm("{ .reg .u64 t; cvta.to.shared.u64 t, %1; cvt.u32.u64 %0, t; }" : "=r"(a) : "l"(p));
    return a;
}
#define LDSM4(r, addr) \
    asm volatile("ldmatrix.sync.aligned.m8n8.x4.shared.b16 {%0,%1,%2,%3}, [%4];" \
        : "=r"((r)[0]), "=r"((r)[1]), "=r"((r)[2]), "=r"((r)[3]) : "r"(addr))
#define MMA16816(acc, a, b0v, b1v) \
    asm volatile("mma.sync.aligned.m16n8k16.row.col.f32.bf16.bf16.f32 " \
        "{%0,%1,%2,%3}, {%4,%5,%6,%7}, {%8,%9}, {%0,%1,%2,%3};" \
        : "+f"((acc)[0]), "+f"((acc)[1]), "+f"((acc)[2]), "+f"((acc)[3]) \
        : "r"((a)[0]), "r"((a)[1]), "r"((a)[2]), "r"((a)[3]), "r"(b0v), "r"(b1v))
#define CP16(dst, src)      asm volatile("cp.async.cg.shared.global [%0], [%1], 16;" :: "r"(dst), "l"(src))
#define CP16Z(dst, src, sz) asm volatile("cp.async.cg.shared.global [%0], [%1], 16, %2;" :: "r"(dst), "l"(src), "r"(sz))
#define CPCOMMIT() asm volatile("cp.async.commit_group;" ::: "memory")
#define CPWAIT1()  asm volatile("cp.async.wait_group 1;" ::: "memory")
#define CPWAIT0()  asm volatile("cp.async.wait_group 0;" ::: "memory")

#define STG_BYTES 40960
#define MMA_SMEM  (2*STG_BYTES)
#define QK_SMEM   (4*128*72*2)
#define PV_STG    (2*128*40*2 + 2*64*40*2)
#define PV_SMEM   (2*PV_STG)

__device__ __forceinline__ void split_w(float x, bf16* oh, bf16* ol){
    bf16 hi = __float2bfloat16(x);
    *oh = hi;
    *ol = __float2bfloat16(x - __bfloat162float(hi));
}

// ---------------- small kernels ----------------

__global__ void k_ropetab(){
    int i = blockIdx.x*blockDim.x + threadIdx.x;
    if (i >= SQ*16) return;
    int j = i & 15, p = i >> 4;
    double ang = (double)p * pow(10000.0, -(double)j/16.0);
    g_cosT[i] = (float)cos(ang); g_sinT[i] = (float)sin(ang);
}

__global__ void k_embed(const int* __restrict__ ids, const float* __restrict__ emb){
    int t = blockIdx.x;
    const float* er = emb + (long)ids[t]*DM;
    for (int d = threadIdx.x; d < DM; d += 256){
        float vv = er[d];
        g_x[(long)t*4096+d] = vv; g_x[(long)t*4096+1024+d] = vv;
        g_x[(long)t*4096+2048+d] = vv; g_x[(long)t*4096+3072+d] = vv;
    }
}

__global__ void k_htrans(const float* __restrict__ src, float* __restrict__ dst, int nout){
    int i = blockIdx.x*blockDim.x + threadIdx.x;
    if (i >= 4096*nout) return;
    int r = i / nout, c = i % nout;
    dst[(long)c*4096 + r] = src[i];
}

// hc raw with fused per-token rms-inverse: raw[t][j] = inv[t]*(x[t].Wt[j]) + b[j]
template<int NOUT>
__global__ void __launch_bounds__(256) k_hcT(const float* __restrict__ Wt, const float* __restrict__ bb,
                                             float* __restrict__ raw){
    __shared__ float sx[16][129];
    __shared__ float sw[128][25];
    __shared__ float sinv[16];
    int t0 = blockIdx.x*16;
    int tid = threadIdx.x;
    int tt = tid & 15, jb = tid >> 4;
    float acc0 = 0.f, acc1 = 0.f, ss = 0.f;
    for (int k0 = 0; k0 < 4096; k0 += 128){
        for (int i = tid; i < 16*128; i += 256){
            int r = i>>7, c = i&127;
            sx[r][c] = g_x[(long)(t0+r)*4096 + k0 + c];
        }
        for (int i = tid; i < 128*NOUT; i += 256){
            int j = i>>7, kk = i&127;
            sw[kk][j] = Wt[(long)j*4096 + k0 + kk];
        }
        __syncthreads();
        #pragma unroll 8
        for (int kk = 0; kk < 128; kk++){
            float xv = sx[tt][kk];
            acc0 += xv*sw[kk][jb];
            if (NOUT > 16) acc1 += xv*sw[kk][jb+16];
            if (jb == 0) ss += xv*xv;
        }
        __syncthreads();
    }
    if (jb == 0) sinv[tt] = rsqrtf(ss/4096.f + 1e-6f);
    __syncthreads();
    float inv = sinv[tt];
    if (jb < NOUT)      raw[(long)(t0+tt)*NOUT + jb]      = inv*acc0 + bb[jb];
    if (NOUT > 16 && jb+16 < NOUT) raw[(long)(t0+tt)*NOUT + jb+16] = inv*acc1 + bb[jb+16];
}

__global__ void k_sink(){
    int t = blockIdx.x*blockDim.x + threadIdx.x;
    if (t >= SQ) return;
    const float* r = g_raw + (long)t*NCH;
    for (int n = 0; n < 4; n++){ g_pre[t*4+n] = 1.f + tanhf(r[n]); g_post[t*4+n] = 1.f + tanhf(r[4+n]); }
    float M[16]; float mx = -1e30f;
    #pragma unroll
    for (int i = 0; i < 16; i++){ float vv = r[8+i] + ((i%5==0)?1.f:0.f); M[i]=vv; if (vv>mx) mx=vv; }
    #pragma unroll
    for (int i = 0; i < 16; i++) M[i] = expf(M[i]-mx);
    for (int it = 0; it < 20; it++){
        #pragma unroll
        for (int n = 0; n < 4; n++){
            float s = M[n*4]+M[n*4+1]+M[n*4+2]+M[n*4+3] + 1e-6f;
            float rr = __frcp_rn(s);
            for (int m = 0; m < 4; m++) M[n*4+m] *= rr;
        }
        #pragma unroll
        for (int m = 0; m < 4; m++){
            float s = M[m]+M[4+m]+M[8+m]+M[12+m] + 1e-6f;
            float rr = __frcp_rn(s);
            for (int n = 0; n < 4; n++) M[n*4+m] *= rr;
        }
    }
    for (int i = 0; i < 16; i++) g_comb[t*16+i] = M[i];
}

// coll + rms + ln, writing fp32 h AND bf16 hi/lo split in one pass
__global__ void k_coll(const float* __restrict__ ln){
    int t = blockIdx.x;
    __shared__ float red[256];
    float p0=g_pre[t*4],p1=g_pre[t*4+1],p2=g_pre[t*4+2],p3=g_pre[t*4+3];
    const float* xt = g_x + (long)t*4096;
    float local[4]; float ss = 0.f;
    #pragma unroll
    for (int c = 0; c < 4; c++){
        int d = threadIdx.x + c*256;
        float vv = p0*xt[d]+p1*xt[1024+d]+p2*xt[2048+d]+p3*xt[3072+d];
        local[c]=vv; ss += vv*vv;
    }
    red[threadIdx.x]=ss; __syncthreads();
    for (int s = 128; s > 0; s >>= 1){ if (threadIdx.x < s) red[threadIdx.x]+=red[threadIdx.x+s]; __syncthreads(); }
    float inv = rsqrtf(red[0]/1024.f + 1e-6f);
    #pragma unroll
    for (int c = 0; c < 4; c++){
        int d = threadIdx.x + c*256;
        float vv = local[c]*inv*ln[d];
        g_h[(long)t*DM+d] = vv;
        split_w(vv, &g_ah[(long)t*DM+d], &g_al[(long)t*DM+d]);
    }
}

// rope + split q/k to bf16 hi/lo in one pass.
__global__ void k_rope_split(){
    int i = blockIdx.x*blockDim.x + threadIdx.x;
    if (i >= SQ*NHD*32) return;
    int j = i & 31, h = (i>>5)&15, s = i>>9;
    long base = (long)s*HHD + h*64;
    if (j < 16){
        float c = g_cosT[s*16+j], sn = g_sinT[s*16+j];
        float x1=g_q[base+j], x2=g_q[base+16+j];
        float q1 = x1*c-x2*sn, q2 = x1*sn+x2*c;
        split_w(q1, &g_qsh[base+j],    &g_qsl[base+j]);
        split_w(q2, &g_qsh[base+16+j], &g_qsl[base+16+j]);
        x1=g_k[base+j]; x2=g_k[base+16+j];
        q1 = x1*c-x2*sn; q2 = x1*sn+x2*c;
        split_w(q1, &g_ksh[base+j],    &g_ksl[base+j]);
        split_w(q2, &g_ksh[base+16+j], &g_ksl[base+16+j]);
    } else {
        int d1 = j + 16;   // 32..47
        int d2 = j + 32;   // 48..63
        split_w(g_q[base+d1], &g_qsh[base+d1], &g_qsl[base+d1]);
        split_w(g_k[base+d1], &g_ksh[base+d1], &g_ksl[base+d1]);
        split_w(g_q[base+d2], &g_qsh[base+d2], &g_qsl[base+d2]);
        split_w(g_k[base+d2], &g_ksh[base+d2], &g_ksl[base+d2]);
    }
}

// ---- HMMA scores: S[128q x 128k] per head, K=64, single stage ----
__global__ void __launch_bounds__(256) k_att_qk(){
    int h = blockIdx.z, q0 = blockIdx.y*128, k0 = blockIdx.x*128;
    if (k0 > q0 + 127) return;
    extern __shared__ char dsm[];
    bf16* sQh = (bf16*)dsm;
    bf16* sQl = sQh + 128*72;
    bf16* sKh = sQl + 128*72;
    bf16* sKl = sKh + 128*72;
    int tid = threadIdx.x, wid = tid>>5, lane = tid&31;
    int r = tid>>1, cb = (tid&1)*32;
    #pragma unroll
    for (int j = 0; j < 4; j++){
        long qoff = (long)(q0+r)*HHD + h*64 + cb + j*8;
        long koff = (long)(k0+r)*HHD + h*64 + cb + j*8;
        CP16(smem_u32(&sQh[r*72 + cb + j*8]), g_qsh + qoff);
        CP16(smem_u32(&sQl[r*72 + cb + j*8]), g_qsl + qoff);
        CP16(smem_u32(&sKh[r*72 + cb + j*8]), g_ksh + koff);
        CP16(smem_u32(&sKl[r*72 + cb + j*8]), g_ksl + koff);
    }
    CPCOMMIT(); CPWAIT0();
    __syncthreads();
    int wm = (wid&3)*32, wn = (wid>>2)*64;
    float acc[2][8][4] = {};
    int qd = lane>>3, lr = lane&7;
    int aRow = lr + (qd&1)*8, aCol = (qd>>1)*8;
    int bRow = lr + (qd>>1)*8, bCol = (qd&1)*8;
    #pragma unroll
    for (int ks = 0; ks < 64; ks += 16){
        unsigned aH[2][4], aL[2][4];
        #pragma unroll
        for (int mt = 0; mt < 2; mt++){
            LDSM4(aH[mt], smem_u32(&sQh[(wm + mt*16 + aRow)*72 + ks + aCol]));
            LDSM4(aL[mt], smem_u32(&sQl[(wm + mt*16 + aRow)*72 + ks + aCol]));
        }
        #pragma unroll
        for (int np = 0; np < 4; np++){
            unsigned bH[4], bL[4];
            LDSM4(bH, smem_u32(&sKh[(wn + np*16 + bRow)*72 + ks + bCol]));
            LDSM4(bL, smem_u32(&sKl[(wn + np*16 + bRow)*72 + ks + bCol]));
            #pragma unroll
            for (int mt = 0; mt < 2; mt++){
                MMA16816(acc[mt][np*2],   aH[mt], bH[0], bH[1]);
                MMA16816(acc[mt][np*2+1], aH[mt], bH[2], bH[3]);
                MMA16816(acc[mt][np*2],   aH[mt], bL[0], bL[1]);
                MMA16816(acc[mt][np*2+1], aH[mt], bL[2], bL[3]);
                MMA16816(acc[mt][np*2],   aL[mt], bH[0], bH[1]);
                MMA16816(acc[mt][np*2+1], aL[mt], bH[2], bH[3]);
            }
        }
    }
    float* out = g_scr + (size_t)h*SQ*SQ;
    #pragma unroll
    for (int mt = 0; mt < 2; mt++){
        size_t row = q0 + wm + mt*16 + (lane>>2);
        #pragma unroll
        for (int nt = 0; nt < 8; nt++){
            size_t col = k0 + wn + nt*8 + (lane&3)*2;
            *(float2*)&out[row*SQ + col]     = make_float2(acc[mt][nt][0]*0.125f, acc[mt][nt][1]*0.125f);
            *(float2*)&out[(row+8)*SQ + col] = make_float2(acc[mt][nt][2]*0.125f, acc[mt][nt][3]*0.125f);
        }
    }
}

// softmax: fp32 scores -> bf16 hi/lo P, zero-filled to 128-tile end
__global__ void k_softmax2(){
    int h = blockIdx.y, qi = blockIdx.x;
    float* row = g_scr + (size_t)h*SQ*SQ + (size_t)qi*SQ;
    bf16* oh = g_ph + (size_t)h*SQ*SQ + (size_t)qi*SQ;
    bf16* ol = g_pl + (size_t)h*SQ*SQ + (size_t)qi*SQ;
    int n = qi + 1;
    __shared__ float red[256];
    float mx = -1e30f;
    for (int i = threadIdx.x; i < n; i += 256) mx = fmaxf(mx, row[i]);
    red[threadIdx.x]=mx; __syncthreads();
    for (int s = 128; s > 0; s >>= 1){ if (threadIdx.x < s) red[threadIdx.x]=fmaxf(red[threadIdx.x],red[threadIdx.x+s]); __syncthreads(); }
    mx = red[0]; __syncthreads();
    float sum = 0.f;
    for (int i = threadIdx.x; i < n; i += 256){ float e = expf(row[i]-mx); row[i]=e; sum+=e; }
    red[threadIdx.x]=sum; __syncthreads();
    for (int s = 128; s > 0; s >>= 1){ if (threadIdx.x < s) red[threadIdx.x]+=red[threadIdx.x+s]; __syncthreads(); }
    float invs = 1.f/red[0];
    for (int i = threadIdx.x; i < n; i += 256){
        float p = row[i]*invs;
        split_w(p, &oh[i], &ol[i]);
    }
    int end = ((qi>>7)+1)<<7;
    bf16 z = __float2bfloat16(0.f);
    for (int i = n + threadIdx.x; i < end; i += 256){ oh[i] = z; ol[i] = z; }
}

// ---- HMMA PV: O[128q x 64d] per head; A=P, B=Vt[d][seq]; 2-stage pipeline ----
__global__ void __launch_bounds__(256) k_att_pv(){
    int q0 = blockIdx.x*128, h = blockIdx.y;
    extern __shared__ char dsm[];
    int tid = threadIdx.x, wid = tid>>5, lane = tid&31;
    int wm = wid*16;
    float acc[8][4] = {};
    int qd = lane>>3, lr = lane&7;
    int aRow = lr + (qd&1)*8, aCol = (qd>>1)*8;
    int bRow = lr + (qd>>1)*8, bCol = (qd&1)*8;
    int r0 = tid>>2, q0i = (tid&3)*8;
    int rb = tid>>2, cbv = (tid&3)*8;
    const bf16* Pbh = g_ph + (size_t)h*SQ*SQ;
    const bf16* Pbl = g_pl + (size_t)h*SQ*SQ;
    const bf16* Vbh = g_vth + (size_t)h*64*SQ;
    const bf16* Vbl = g_vtl + (size_t)h*64*SQ;

    #define PV_LOAD(s, kc) do { \
        bf16* _ph = (bf16*)(dsm + (s)*PV_STG); \
        bf16* _pl = (bf16*)(dsm + (s)*PV_STG + 10240); \
        bf16* _vh = (bf16*)(dsm + (s)*PV_STG + 20480); \
        bf16* _vl = (bf16*)(dsm + (s)*PV_STG + 25600); \
        CP16(smem_u32(&_ph[r0*40 + q0i]), Pbh + (size_t)(q0+r0)*SQ + (kc) + q0i); \
        CP16(smem_u32(&_ph[(r0+64)*40 + q0i]), Pbh + (size_t)(q0+r0+64)*SQ + (kc) + q0i); \
        CP16(smem_u32(&_pl[r0*40 + q0i]), Pbl + (size_t)(q0+r0)*SQ + (kc) + q0i); \
        CP16(smem_u32(&_pl[(r0+64)*40 + q0i]), Pbl + (size_t)(q0+r0+64)*SQ + (kc) + q0i); \
        CP16(smem_u32(&_vh[rb*40 + cbv]), Vbh + (size_t)rb*SQ + (kc) + cbv); \
        CP16(smem_u32(&_vl[rb*40 + cbv]), Vbl + (size_t)rb*SQ + (kc) + cbv); \
    } while(0)

    int nk = (q0 + 128) >> 5;
    PV_LOAD(0, 0);
    CPCOMMIT();
    for (int t = 0; t < nk; t++){
        int buf = t & 1;
        if (t+1 < nk){
            PV_LOAD(buf^1, (t+1)<<5);
            CPCOMMIT();
            CPWAIT1();
        } else {
            CPWAIT0();
        }
        __syncthreads();
        bf16* sPh = (bf16*)(dsm + buf*PV_STG);
        bf16* sPl = (bf16*)(dsm + buf*PV_STG + 10240);
        bf16* sVh = (bf16*)(dsm + buf*PV_STG + 20480);
        bf16* sVl = (bf16*)(dsm + buf*PV_STG + 25600);
        #pragma unroll
        for (int ks = 0; ks < 32; ks += 16){
            unsigned aH[4], aL[4];
            LDSM4(aH, smem_u32(&sPh[(wm + aRow)*40 + ks + aCol]));
            LDSM4(aL, smem_u32(&sPl[(wm + aRow)*40 + ks + aCol]));
            #pragma unroll
            for (int np = 0; np < 4; np++){
                unsigned bH[4], bL[4];
                LDSM4(bH, smem_u32(&sVh[(np*16 + bRow)*40 + ks + bCol]));
                LDSM4(bL, smem_u32(&sVl[(np*16 + bRow)*40 + ks + bCol]));
                MMA16816(acc[np*2],   aH, bH[0], bH[1]);
                MMA16816(acc[np*2+1], aH, bH[2], bH[3]);
                MMA16816(acc[np*2],   aH, bL[0], bL[1]);
                MMA16816(acc[np*2+1], aH, bL[2], bL[3]);
                MMA16816(acc[np*2],   aL, bH[0], bH[1]);
                MMA16816(acc[np*2+1], aL, bH[2], bH[3]);
            }
        }
        __syncthreads();
    }
    #undef PV_LOAD
    #pragma unroll
    for (int half = 0; half < 2; half++){
        long row = q0 + wm + half*8 + (lane>>2);
        #pragma unroll
        for (int nt = 0; nt < 8; nt++){
            long col = h*64 + nt*8 + (lane&3)*2;
            float v0 = acc[nt][half*2], v1 = acc[nt][half*2+1];
            split_w(v0, &g_aoh[row*HHD + col],   &g_aol[row*HHD + col]);
            split_w(v1, &g_aoh[row*HHD + col+1], &g_aol[row*HHD + col+1]);
        }
    }
}

// combine (+ optional MoE routed add fused): x[m] = post[m]*(a [+ routed]) + comb^T x
__global__ void k_combine(int moe){
    int t = blockIdx.x;
    float ps[4], cb[16];
    #pragma unroll
    for (int n = 0; n < 4; n++) ps[n] = g_post[t*4+n];
    #pragma unroll
    for (int i = 0; i < 16; i++) cb[i] = g_comb[t*16+i];
    int e0 = 0, e1 = 0; float w0 = 0.f, w1 = 0.f;
    if (moe){
        e0 = g_eof[t*2]; e1 = g_eof[t*2+1];
        w0 = g_ew[t*2];  w1 = g_ew[t*2+1];
    }
    for (int d = threadIdx.x; d < DM; d += 256){
        float xv[4];
        #pragma unroll
        for (int n = 0; n < 4; n++) xv[n] = g_x[(long)t*4096 + n*1024 + d];
        float av = g_a[(long)t*DM + d];
        if (moe) av += w0*g_ed[(long)e0*DM+d] + w1*g_ed[(long)e1*DM+d];
        #pragma unroll
        for (int m = 0; m < 4; m++){
            float s = ps[m]*av;
            #pragma unroll
            for (int n = 0; n < 4; n++) s += cb[n*4+m]*xv[n];
            g_x[(long)t*4096 + m*1024 + d] = s;
        }
    }
}

__global__ void k_reset(){
    int i = blockIdx.x*blockDim.x + threadIdx.x;
    if (i < NEXP){ g_cnt[i]=0; g_fill[i]=0; }
    if (i < MAXENT) g_etok[i] = -1;
}

__global__ void k_gate(const float* __restrict__ gw, const int* __restrict__ ids,
                       const int* __restrict__ t2e, int layer){
    int t = blockIdx.x;
    __shared__ float sm[256][8];
    __shared__ float sc[8];
    float acc[8] = {};
    const float* xt = g_h + (long)t*DM;
    for (int i = threadIdx.x; i < DM; i += 256){
        float vv = xt[i];
        #pragma unroll
        for (int e = 0; e < 8; e++) acc[e] += vv*gw[e*DM+i];
    }
    #pragma unroll
    for (int e = 0; e < 8; e++) sm[threadIdx.x][e] = acc[e];
    __syncthreads();
    if (threadIdx.x < 8){
        float s = 0.f;
        for (int r = 0; r < 256; r++) s += sm[r][threadIdx.x];
        float sp = (s > 20.f) ? s : log1pf(expf(s));
        sc[threadIdx.x] = sqrtf(sp);
    }
    __syncthreads();
    if (threadIdx.x == 0){
        int i0, i1;
        if (layer < 1){ int id = ids[t]; i0 = t2e[id*2]; i1 = t2e[id*2+1]; }
        else {
            i0 = 0;
            for (int e = 1; e < 8; e++) if (sc[e] > sc[i0]) i0 = e;
            i1 = -1; float best = -1e30f;
            for (int e = 0; e < 8; e++){ if (e==i0) continue; if (sc[e] > best){ best = sc[e]; i1 = e; } }
        }
        float w0 = sc[i0], w1 = sc[i1];
        float sw = w0 + w1 + 1e-20f;
        g_ew[t*2] = w0/sw*2.5f; g_ew[t*2+1] = w1/sw*2.5f;
        g_eidx[t*2] = i0; g_eidx[t*2+1] = i1;
        atomicAdd(&g_cnt[i0], 1); atomicAdd(&g_cnt[i1], 1);
    }
}

__global__ void k_off(){
    if (threadIdx.x == 0){
        int o = 0;
        for (int e = 0; e < NEXP; e++){ g_off[e] = o; o += ((g_cnt[e]+127)/128)*128; }
        g_off[NEXP] = o;
    }
}

__global__ void k_scatter(){
    int i = blockIdx.x*blockDim.x + threadIdx.x;
    if (i >= SQ*KSEL) return;
    int e = g_eidx[i];
    int pos = g_off[e] + atomicAdd(&g_fill[e], 1);
    g_etok[pos] = i >> 1;
    g_eof[i] = pos;
}

__global__ void k_silu_split(const float* __restrict__ g, const float* __restrict__ u,
                             bf16* __restrict__ oh, bf16* __restrict__ ol, int n){
    int i = blockIdx.x*blockDim.x + threadIdx.x;
    if (i >= n) return;
    float x = g[i];
    float s = (x / (1.f + expf(-x))) * u[i];
    split_w(s, &oh[i], &ol[i]);
}

// transpose + split with vectorized bf16x2 stores
__global__ void k_tsplit(const float* __restrict__ src, bf16* __restrict__ dh, bf16* __restrict__ dl,
                         int K, int N){
    long zo = (long)blockIdx.z * K * N;
    src += zo; dh += zo; dl += zo;
    __shared__ float t[32][33];
    int n0 = blockIdx.x*32, k0 = blockIdx.y*32;
    int tx = threadIdx.x, ty = threadIdx.y;
    #pragma unroll
    for (int j = 0; j < 4; j++)
        t[ty + j*8][tx] = src[(long)(k0 + ty + j*8)*N + n0 + tx];
    __syncthreads();
    int k2 = (tx & 15)*2, half = tx >> 4;
    #pragma unroll
    for (int j = 0; j < 2; j++){
        int nn = ty + j*8 + half*16;
        float f0 = t[k2][nn],   f1 = t[k2+1][nn];
        bf16 h0 = __float2bfloat16(f0), h1 = __float2bfloat16(f1);
        bf16 l0 = __float2bfloat16(f0 - __bfloat162float(h0));
        bf16 l1 = __float2bfloat16(f1 - __bfloat162float(h1));
        long o = (long)(n0 + nn)*K + k0 + k2;
        __nv_bfloat162 hv; hv.x = h0; hv.y = h1;
        __nv_bfloat162 lv; lv.x = l0; lv.y = l1;
        *(__nv_bfloat162*)&dh[o] = hv;
        *(__nv_bfloat162*)&dl[o] = lv;
    }
}

// final head collapse + rms + final_norm, writing split bf16 directly
__global__ void k_final(const float* __restrict__ fw){
    int t = blockIdx.x;
    __shared__ float red[256];
    float p[4];
    #pragma unroll
    for (int n = 0; n < 4; n++) p[n] = 1.f + tanhf(g_raw[t*4+n]);
    const float* xt = g_x + (long)t*4096;
    float local[4]; float ss = 0.f;
    #pragma unroll
    for (int c = 0; c < 4; c++){
        int d = threadIdx.x + c*256;
        float vv = p[0]*xt[d]+p[1]*xt[1024+d]+p[2]*xt[2048+d]+p[3]*xt[3072+d];
        local[c]=vv; ss += vv*vv;
    }
    red[threadIdx.x]=ss; __syncthreads();
    for (int s = 128; s > 0; s >>= 1){ if (threadIdx.x < s) red[threadIdx.x]+=red[threadIdx.x+s]; __syncthreads(); }
    float inv = rsqrtf(red[0]/1024.f + 1e-6f);
    #pragma unroll
    for (int c = 0; c < 4; c++){
        int d = threadIdx.x + c*256;
        float vv = local[c]*inv*fw[d];
        split_w(vv, &g_ah[(long)t*DM+d], &g_al[(long)t*DM+d]);
    }
}

// ---------------- pipelined HMMA GEMM: C[M,N] = A[M,K] x B[N,K]^T ----------------
__global__ void __launch_bounds__(256) k_mma(const bf16* __restrict__ Ah, const bf16* __restrict__ Al,
                                             const bf16* __restrict__ Bh, const bf16* __restrict__ Bl,
                                             float* __restrict__ C, int N, int K){
    extern __shared__ char dsm[];
    int tid = threadIdx.x, wid = tid>>5, lane = tid&31;
    int m0 = blockIdx.y*128, n0 = blockIdx.x*128;
    int wm = (wid&3)*32, wn = (wid>>2)*64;
    float acc[2][8][4] = {};
    int qd = lane>>3, lr = lane&7;
    int aRow = lr + (qd&1)*8, aCol = (qd>>1)*8;
    int bRow = lr + (qd>>1)*8, bCol = (qd&1)*8;
    int r0 = tid>>2, q0i = (tid&3)*8;
    int r1 = r0 + 64;

    #define LOAD_STAGE(s, kc) do { \
        bf16* _ah = (bf16*)(dsm + (s)*STG_BYTES); \
        bf16* _al = (bf16*)(dsm + (s)*STG_BYTES + 10240); \
        bf16* _bh = (bf16*)(dsm + (s)*STG_BYTES + 20480); \
        bf16* _bl = (bf16*)(dsm + (s)*STG_BYTES + 30720); \
        CP16(smem_u32(&_ah[r0*40 + q0i]), Ah + (long)(m0+r0)*K + (kc) + q0i); \
        CP16(smem_u32(&_ah[r1*40 + q0i]), Ah + (long)(m0+r1)*K + (kc) + q0i); \
        CP16(smem_u32(&_al[r0*40 + q0i]), Al + (long)(m0+r0)*K + (kc) + q0i); \
        CP16(smem_u32(&_al[r1*40 + q0i]), Al + (long)(m0+r1)*K + (kc) + q0i); \
        CP16(smem_u32(&_bh[r0*40 + q0i]), Bh + (long)(n0+r0)*K + (kc) + q0i); \
        CP16(smem_u32(&_bh[r1*40 + q0i]), Bh + (long)(n0+r1)*K + (kc) + q0i); \
        CP16(smem_u32(&_bl[r0*40 + q0i]), Bl + (long)(n0+r0)*K + (kc) + q0i); \
        CP16(smem_u32(&_bl[r1*40 + q0i]), Bl + (long)(n0+r1)*K + (kc) + q0i); \
    } while(0)

    LOAD_STAGE(0, 0);
    CPCOMMIT();
    int nk = K >> 5;
    for (int t = 0; t < nk; t++){
        int buf = t & 1;
        if (t+1 < nk){
            LOAD_STAGE(buf^1, (t+1)<<5);
            CPCOMMIT();
            CPWAIT1();
        } else {
            CPWAIT0();
        }
        __syncthreads();
        bf16* sAh = (bf16*)(dsm + buf*STG_BYTES);
        bf16* sAl = (bf16*)(dsm + buf*STG_BYTES + 10240);
        bf16* sBh = (bf16*)(dsm + buf*STG_BYTES + 20480);
        bf16* sBl = (bf16*)(dsm + buf*STG_BYTES + 30720);
        #pragma unroll
        for (int ks = 0; ks < 32; ks += 16){
            unsigned aH[2][4], aL[2][4];
            #pragma unroll
            for (int mt = 0; mt < 2; mt++){
                LDSM4(aH[mt], smem_u32(&sAh[(wm + mt*16 + aRow)*40 + ks + aCol]));
                LDSM4(aL[mt], smem_u32(&sAl[(wm + mt*16 + aRow)*40 + ks + aCol]));
            }
            #pragma unroll
            for (int np = 0; np < 4; np++){
                unsigned bH[4], bL[4];
                LDSM4(bH, smem_u32(&sBh[(wn + np*16 + bRow)*40 + ks + bCol]));
                LDSM4(bL, smem_u32(&sBl[(wn + np*16 + bRow)*40 + ks + bCol]));
                #pragma unroll
                for (int mt = 0; mt < 2; mt++){
                    MMA16816(acc[mt][np*2],   aH[mt], bH[0], bH[1]);
                    MMA16816(acc[mt][np*2+1], aH[mt], bH[2], bH[3]);
                    MMA16816(acc[mt][np*2],   aH[mt], bL[0], bL[1]);
                    MMA16816(acc[mt][np*2+1], aH[mt], bL[2], bL[3]);
                    MMA16816(acc[mt][np*2],   aL[mt], bH[0], bH[1]);
                    MMA16816(acc[mt][np*2+1], aL[mt], bH[2], bH[3]);
                }
            }
        }
        __syncthreads();
    }
    #undef LOAD_STAGE
    #pragma unroll
    for (int mt = 0; mt < 2; mt++){
        long row = m0 + wm + mt*16 + (lane>>2);
        #pragma unroll
        for (int nt = 0; nt < 8; nt++){
            long col = n0 + wn + nt*8 + (lane&3)*2;
            *(float2*)&C[row*N + col]     = make_float2(acc[mt][nt][0], acc[mt][nt][1]);
            *(float2*)&C[(row+8)*N + col] = make_float2(acc[mt][nt][2], acc[mt][nt][3]);
        }
    }
}

// pipelined segmented (per-expert) HMMA GEMM with optional token gather on A
__global__ void __launch_bounds__(256) k_mma_seg(const bf16* __restrict__ Ah, const bf16* __restrict__ Al,
                                                 const bf16* __restrict__ Bh0, const bf16* __restrict__ Bl0,
                                                 float* __restrict__ C, int N, int K, long Bstride, int useGather){
    int e = blockIdx.z;
    int seg0 = g_off[e], nrows = g_cnt[e];
    int m0 = blockIdx.y*128;
    if (m0 >= nrows) return;
    int n0 = blockIdx.x*128;
    const bf16* Bh = Bh0 + (long)e*Bstride;
    const bf16* Bl = Bl0 + (long)e*Bstride;
    extern __shared__ char dsm[];
    int tid = threadIdx.x, wid = tid>>5, lane = tid&31;
    int wm = (wid&3)*32, wn = (wid>>2)*64;
    float acc[2][8][4] = {};
    int qd = lane>>3, lr = lane&7;
    int aRow = lr + (qd&1)*8, aCol = (qd>>1)*8;
    int bRow = lr + (qd>>1)*8, bCol = (qd&1)*8;
    int r0 = tid>>2, q0i = (tid&3)*8;
    int r1 = r0 + 64;
    const bf16 *a0h, *a0l, *a1h, *a1l;
    unsigned sz0 = 16, sz1 = 16;
    {
        int ge0 = seg0 + m0 + r0, ge1 = seg0 + m0 + r1;
        if (useGather){
            int tk0 = g_etok[ge0], tk1 = g_etok[ge1];
            if (tk0 >= 0){ a0h = Ah + (long)tk0*K; a0l = Al + (long)tk0*K; } else { a0h = Ah; a0l = Al; sz0 = 0; }
            if (tk1 >= 0){ a1h = Ah + (long)tk1*K; a1l = Al + (long)tk1*K; } else { a1h = Ah; a1l = Al; sz1 = 0; }
        } else {
            a0h = Ah + (long)ge0*K; a0l = Al + (long)ge0*K;
            a1h = Ah + (long)ge1*K; a1l = Al + (long)ge1*K;
        }
    }

    #define LOAD_STAGE_S(s, kc) do { \
        bf16* _ah = (bf16*)(dsm + (s)*STG_BYTES); \
        bf16* _al = (bf16*)(dsm + (s)*STG_BYTES + 10240); \
        bf16* _bh = (bf16*)(dsm + (s)*STG_BYTES + 20480); \
        bf16* _bl = (bf16*)(dsm + (s)*STG_BYTES + 30720); \
        CP16Z(smem_u32(&_ah[r0*40 + q0i]), a0h + (kc) + q0i, sz0); \
        CP16Z(smem_u32(&_ah[r1*40 + q0i]), a1h + (kc) + q0i, sz1); \
        CP16Z(smem_u32(&_al[r0*40 + q0i]), a0l + (kc) + q0i, sz0); \
        CP16Z(smem_u32(&_al[r1*40 + q0i]), a1l + (kc) + q0i, sz1); \
        CP16(smem_u32(&_bh[r0*40 + q0i]), Bh + (long)(n0+r0)*K + (kc) + q0i); \
        CP16(smem_u32(&_bh[r1*40 + q0i]), Bh + (long)(n0+r1)*K + (kc) + q0i); \
        CP16(smem_u32(&_bl[r0*40 + q0i]), Bl + (long)(n0+r0)*K + (kc) + q0i); \
        CP16(smem_u32(&_bl[r1*40 + q0i]), Bl + (long)(n0+r1)*K + (kc) + q0i); \
    } while(0)

    LOAD_STAGE_S(0, 0);
    CPCOMMIT();
    int nk = K >> 5;
    for (int t = 0; t < nk; t++){
        int buf = t & 1;
        if (t+1 < nk){
            LOAD_STAGE_S(buf^1, (t+1)<<5);
            CPCOMMIT();
            CPWAIT1();
        } else {
            CPWAIT0();
        }
        __syncthreads();
        bf16* sAh = (bf16*)(dsm + buf*STG_BYTES);
        bf16* sAl = (bf16*)(dsm + buf*STG_BYTES + 10240);
        bf16* sBh = (bf16*)(dsm + buf*STG_BYTES + 20480);
        bf16* sBl = (bf16*)(dsm + buf*STG_BYTES + 30720);
        #pragma unroll
        for (int ks = 0; ks < 32; ks += 16){
            unsigned aH[2][4], aL[2][4];
            #pragma unroll
            for (int mt = 0; mt < 2; mt++){
                LDSM4(aH[mt], smem_u32(&sAh[(wm + mt*16 + aRow)*40 + ks + aCol]));
                LDSM4(aL[mt], smem_u32(&sAl[(wm + mt*16 + aRow)*40 + ks + aCol]));
            }
            #pragma unroll
            for (int np = 0; np < 4; np++){
                unsigned bH[4], bL[4];
                LDSM4(bH, smem_u32(&sBh[(wn + np*16 + bRow)*40 + ks + bCol]));
                LDSM4(bL, smem_u32(&sBl[(wn + np*16 + bRow)*40 + ks + bCol]));
                #pragma unroll
                for (int mt = 0; mt < 2; mt++){
                    MMA16816(acc[mt][np*2],   aH[mt], bH[0], bH[1]);
                    MMA16816(acc[mt][np*2+1], aH[mt], bH[2], bH[3]);
                    MMA16816(acc[mt][np*2],   aH[mt], bL[0], bL[1]);
                    MMA16816(acc[mt][np*2+1], aH[mt], bL[2], bL[3]);
                    MMA16816(acc[mt][np*2],   aL[mt], bH[0], bH[1]);
                    MMA16816(acc[mt][np*2+1], aL[mt], bH[2], bH[3]);
                }
            }
        }
        __syncthreads();
    }
    #undef LOAD_STAGE_S
    #pragma unroll
    for (int mt = 0; mt < 2; mt++){
        long row = seg0 + m0 + wm + mt*16 + (lane>>2);
        #pragma unroll
        for (int nt = 0; nt < 8; nt++){
            long col = n0 + wn + nt*8 + (lane&3)*2;
            *(float2*)&C[row*N + col]     = make_float2(acc[mt][nt][0], acc[mt][nt][1]);
            *(float2*)&C[(row+8)*N + col] = make_float2(acc[mt][nt][2], acc[mt][nt][3]);
        }
    }
}

static float* SYM(const void* symbol){
    void* p = nullptr;
    cudaGetSymbolAddress(&p, symbol);
    return (float*)p;
}

extern "C" void kernel_launch(void* const* d_in, const int* in_sizes, int n_in,
                              void* d_out, int out_size){
    const int*   ids    = (const int*)d_in[0];
    const int*   t2e    = (const int*)d_in[1];
    const float* embed  = (const float*)d_in[2];
    const float* ahw    = (const float*)d_in[3];
    const float* ahb    = (const float*)d_in[4];
    const float* fhw    = (const float*)d_in[5];
    const float* fhb    = (const float*)d_in[6];
    const float* ln1    = (const float*)d_in[7];
    const float* ln2    = (const float*)d_in[8];
    const float* wq     = (const float*)d_in[9];
    const float* wk     = (const float*)d_in[10];
    const float* wv     = (const float*)d_in[11];
    const float* wo     = (const float*)d_in[12];
    const float* gatew  = (const float*)d_in[13];
    const float* wge    = (const float*)d_in[14];
    const float* wue    = (const float*)d_in[15];
    const float* wde    = (const float*)d_in[16];
    const float* wgs    = (const float*)d_in[17];
    const float* wus    = (const float*)d_in[18];
    const float* wds    = (const float*)d_in[19];
    const float* headw  = (const float*)d_in[20];
    const float* headb  = (const float*)d_in[21];
    const float* fnw    = (const float*)d_in[22];
    const float* lmh    = (const float*)d_in[23];
    float* out = (float*)d_out;

    float* ph   = SYM(g_h);
    float* pq   = SYM(g_q);
    float* pk   = SYM(g_k);
    float* pv   = SYM(g_v);
    float* pa   = SYM(g_a);
    float* peg  = SYM(g_eg);
    float* peu  = SYM(g_eu);
    float* ped  = SYM(g_ed);
    float* ps1  = SYM(g_s1);
    float* ps2  = SYM(g_s2);
    float* praw = SYM(g_raw);
    float* ptah = SYM(t_ahw);
    float* ptfh = SYM(t_fhw);
    float* pthw = SYM(t_hw);
    bf16* pah  = (bf16*)SYM(g_ah);   bf16* pal  = (bf16*)SYM(g_al);
    bf16* paoh = (bf16*)SYM(g_aoh);  bf16* paol = (bf16*)SYM(g_aol);
    bf16* ps1h = (bf16*)SYM(g_s1h);  bf16* ps1l = (bf16*)SYM(g_s1l);
    bf16* pegh = (bf16*)SYM(g_egh);  bf16* pegl = (bf16*)SYM(g_egl);
    bf16* pvth = (bf16*)SYM(g_vth);  bf16* pvtl = (bf16*)SYM(g_vtl);
    bf16* pbh  = (bf16*)SYM(g_bh);   bf16* pbl  = (bf16*)SYM(g_bl);
    bf16* pqh  = (bf16*)SYM(twqh);   bf16* pql  = (bf16*)SYM(twql);
    bf16* pkh  = (bf16*)SYM(twkh);   bf16* pkl  = (bf16*)SYM(twkl);
    bf16* pvh  = (bf16*)SYM(twvh);   bf16* pvl  = (bf16*)SYM(twvl);
    bf16* poh  = (bf16*)SYM(twoh);   bf16* pol  = (bf16*)SYM(twol);
    bf16* pgsh = (bf16*)SYM(twgsh);  bf16* pgsl = (bf16*)SYM(twgsl);
    bf16* push = (bf16*)SYM(twush);  bf16* pusl = (bf16*)SYM(twusl);
    bf16* pdsh = (bf16*)SYM(twdsh);  bf16* pdsl = (bf16*)SYM(twdsl);
    bf16* pgeh = (bf16*)SYM(twgeh);  bf16* pgel = (bf16*)SYM(twgel);
    bf16* pueh = (bf16*)SYM(twueh);  bf16* puel = (bf16*)SYM(twuel);
    bf16* pdeh = (bf16*)SYM(twdeh);  bf16* pdel = (bf16*)SYM(twdel);

    cudaFuncSetAttribute(k_mma,     cudaFuncAttributeMaxDynamicSharedMemorySize, MMA_SMEM);
    cudaFuncSetAttribute(k_mma_seg, cudaFuncAttributeMaxDynamicSharedMemorySize, MMA_SMEM);
    cudaFuncSetAttribute(k_att_qk,  cudaFuncAttributeMaxDynamicSharedMemorySize, QK_SMEM);
    cudaFuncSetAttribute(k_att_pv,  cudaFuncAttributeMaxDynamicSharedMemorySize, PV_SMEM);

    dim3 tb(32,8);
    // ---- weight prep ----
    k_tsplit<<<dim3(VOC/32, DM/32), tb>>>(lmh, pbh, pbl, DM, VOC);
    for (int l = 0; l < NLAY; l++){
        long o1 = (long)l*DM*HHD, oS = (long)l*FF*DM, oE = (long)l*NEXP*FF*DM;
        k_tsplit<<<dim3(32,32), tb>>>(wq + o1, pqh + o1, pql + o1, DM, HHD);
        k_tsplit<<<dim3(32,32), tb>>>(wk + o1, pkh + o1, pkl + o1, DM, HHD);
        k_tsplit<<<dim3(32,32), tb>>>(wv + o1, pvh + o1, pvl + o1, DM, HHD);
        k_tsplit<<<dim3(32,32), tb>>>(wo + o1, poh + o1, pol + o1, HHD, DM);
        k_tsplit<<<dim3(16,32), tb>>>(wgs + oS, pgsh + oS, pgsl + oS, DM, FF);
        k_tsplit<<<dim3(16,32), tb>>>(wus + oS, push + oS, pusl + oS, DM, FF);
        k_tsplit<<<dim3(32,16), tb>>>(wds + oS, pdsh + oS, pdsl + oS, FF, DM);
        k_tsplit<<<dim3(16,32,8), tb>>>(wge + oE, pgeh + oE, pgel + oE, DM, FF);
        k_tsplit<<<dim3(16,32,8), tb>>>(wue + oE, pueh + oE, puel + oE, DM, FF);
        k_tsplit<<<dim3(32,16,8), tb>>>(wde + oE, pdeh + oE, pdel + oE, FF, DM);
        k_htrans<<<(4096*NCH+255)/256, 256>>>(ahw + (long)l*4096*NCH, ptah + (long)l*NCH*4096, NCH);
        k_htrans<<<(4096*NCH+255)/256, 256>>>(fhw + (long)l*4096*NCH, ptfh + (long)l*NCH*4096, NCH);
    }
    k_htrans<<<(4096*4+255)/256, 256>>>(headw, pthw, 4);

    k_ropetab<<<(SQ*16+255)/256, 256>>>();
    k_embed<<<SQ, 256>>>(ids, embed);

    dim3 gm_1024(8, 16);
    dim3 gm_512 (4, 16);
    dim3 gms_ff (4, MAXENT/128, 8);
    dim3 gms_dm (8, MAXENT/128, 8);
    dim3 gqk(16, 16, 16);
    dim3 gsm(SQ, 16);
    dim3 gpv(16, 16);

    for (int l = 0; l < NLAY; l++){
        long o1 = (long)l*DM*HHD, oS = (long)l*FF*DM, oE = (long)l*NEXP*FF*DM;
        // attention block
        k_hcT<NCH><<<SQ/16, 256>>>(ptah + (long)l*NCH*4096, ahb + l*NCH, praw);
        k_sink<<<(SQ+255)/256, 256>>>();
        k_coll<<<SQ, 256>>>(ln1 + l*DM);
        k_mma<<<gm_1024, 256, MMA_SMEM>>>(pah, pal, pqh + o1, pql + o1, pq, HHD, DM);
        k_mma<<<gm_1024, 256, MMA_SMEM>>>(pah, pal, pkh + o1, pkl + o1, pk, HHD, DM);
        k_mma<<<gm_1024, 256, MMA_SMEM>>>(pah, pal, pvh + o1, pvl + o1, pv, HHD, DM);
        k_rope_split<<<(SQ*NHD*32+255)/256, 256>>>();
        k_tsplit<<<dim3(HHD/32, SQ/32), tb>>>(pv, pvth, pvtl, SQ, HHD);
        k_att_qk<<<gqk, 256, QK_SMEM>>>();
        k_softmax2<<<gsm, 256>>>();
        k_att_pv<<<gpv, 256, PV_SMEM>>>();
        k_mma<<<gm_1024, 256, MMA_SMEM>>>(paoh, paol, poh + o1, pol + o1, pa, DM, HHD);
        k_combine<<<SQ, 256>>>(0);
        // ffn block
        k_hcT<NCH><<<SQ/16, 256>>>(ptfh + (long)l*NCH*4096, fhb + l*NCH, praw);
        k_sink<<<(SQ+255)/256, 256>>>();
        k_coll<<<SQ, 256>>>(ln2 + l*DM);
        k_reset<<<(MAXENT+255)/256, 256>>>();
        k_gate<<<SQ, 256>>>(gatew + (long)l*NEXP*DM, ids, t2e, l);
        k_off<<<1, 32>>>();
        k_scatter<<<(SQ*KSEL+255)/256, 256>>>();
        k_mma_seg<<<gms_ff, 256, MMA_SMEM>>>(pah, pal, pgeh + oE, pgel + oE, peg, FF, DM, (long)FF*DM, 1);
        k_mma_seg<<<gms_ff, 256, MMA_SMEM>>>(pah, pal, pueh + oE, puel + oE, peu, FF, DM, (long)FF*DM, 1);
        k_silu_split<<<((long)MAXENT*FF+255)/256, 256>>>(peg, peu, pegh, pegl, MAXENT*FF);
        k_mma_seg<<<gms_dm, 256, MMA_SMEM>>>(pegh, pegl, pdeh + oE, pdel + oE, ped, DM, FF, (long)DM*FF, 0);
        k_mma<<<gm_512, 256, MMA_SMEM>>>(pah, pal, pgsh + oS, pgsl + oS, ps1, FF, DM);
        k_mma<<<gm_512, 256, MMA_SMEM>>>(pah, pal, push + oS, pusl + oS, ps2, FF, DM);
        k_silu_split<<<(SQ*FF+255)/256, 256>>>(ps1, ps2, ps1h, ps1l, SQ*FF);
        k_mma<<<gm_1024, 256, MMA_SMEM>>>(ps1h, ps1l, pdsh + oS, pdsl + oS, pa, DM, FF);
        k_combine<<<SQ, 256>>>(1);
    }

    // final head + lm head
    k_hcT<4><<<SQ/16, 256>>>(pthw, headb, praw);
    k_final<<<SQ, 256>>>(fnw);
    dim3 glm(VOC/128, SQ/128);
    k_mma<<<glm, 256, MMA_SMEM>>>(pah, pal, pbh, pbl, out, VOC, DM);
}

// round 17
// speedup vs baseline: 1.1433x; 1.0440x over previous
#include <cuda_runtime.h>
#include <cuda_bf16.h>
#include <math.h>

#define SQ 2048
#define DM 1024
#define NS 4
#define NCH 24
#define NLAY 2
#define NHD 16
#define HHD 1024
#define NEXP 8
#define KSEL 2
#define FF 512
#define VOC 32000
#define MAXENT (SQ*KSEL + NEXP*128)
#define SCRN (16ULL*2048ULL*2048ULL)

typedef unsigned long long ull;
typedef __nv_bfloat16 bf16;

__device__ float g_x[SQ*NS*DM];
__device__ float g_raw[SQ*NCH];
__device__ float g_pre[SQ*NS];
__device__ float g_post[SQ*NS];
__device__ float g_comb[SQ*NS*NS];
__device__ float g_h[SQ*DM];
__device__ float g_qkv[SQ*3*HHD];
__device__ float g_scr[SCRN];
__device__ float g_a[SQ*DM];
__device__ float g_cosT[SQ*16];
__device__ float g_sinT[SQ*16];
__device__ int   g_eidx[SQ*KSEL];
__device__ float g_ew[SQ*KSEL];
__device__ int   g_cnt[NEXP];
__device__ int   g_off[NEXP+1];
__device__ int   g_fill[NEXP];
__device__ int   g_etok[MAXENT];
__device__ int   g_eof[SQ*KSEL];
__device__ float g_eg[(size_t)MAXENT*1024];
__device__ float g_ed[(size_t)MAXENT*DM];
__device__ float g_s1[SQ*1024];
__device__ float t_ahw[NLAY*NCH*4096];
__device__ float t_fhw[NLAY*NCH*4096];
__device__ float t_hw[4*4096];
__device__ bf16 g_ah[SQ*DM],  g_al[SQ*DM];
__device__ bf16 g_aoh[SQ*HHD], g_aol[SQ*HHD];
__device__ bf16 g_s1h[SQ*FF],  g_s1l[SQ*FF];
__device__ bf16 g_egh[(size_t)MAXENT*FF], g_egl[(size_t)MAXENT*FF];
// attention bf16 operands
__device__ bf16 g_qsh[SQ*HHD], g_qsl[SQ*HHD];
__device__ bf16 g_ksh[SQ*HHD], g_ksl[SQ*HHD];
__device__ bf16 g_vth[HHD*SQ], g_vtl[HHD*SQ];
__device__ bf16 g_ph[SCRN], g_pl[SCRN];
__device__ bf16 g_bh[(size_t)VOC*DM], g_bl[(size_t)VOC*DM];
__device__ bf16 twqkvh[(size_t)NLAY*3*HHD*DM], twqkvl[(size_t)NLAY*3*HHD*DM];
__device__ bf16 twoh[NLAY*DM*HHD], twol[NLAY*DM*HHD];
__device__ bf16 twgush[NLAY*1024*DM], twgusl[NLAY*1024*DM];
__device__ bf16 twdsh[NLAY*DM*FF], twdsl[NLAY*DM*FF];
__device__ bf16 twgueh[(size_t)NLAY*NEXP*1024*DM], twguel[(size_t)NLAY*NEXP*1024*DM];
__device__ bf16 twdeh[(size_t)NLAY*NEXP*DM*FF], twdel[(size_t)NLAY*NEXP*DM*FF];

// ---- HMMA / cp.async helpers ----
__device__ __forceinline__ unsigned smem_u32(const void* p){
    unsigned a;
    asm("{ .reg .u64 t; cvta.to.shared.u64 t, %1; cvt.u32.u64 %0, t; }" : "=r"(a) : "l"(p));
    return a;
}
#define LDSM4(r, addr) \
    asm volatile("ldmatrix.sync.aligned.m8n8.x4.shared.b16 {%0,%1,%2,%3}, [%4];" \
        : "=r"((r)[0]), "=r"((r)[1]), "=r"((r)[2]), "=r"((r)[3]) : "r"(addr))
#define MMA16816(acc, a, b0v, b1v) \
    asm volatile("mma.sync.aligned.m16n8k16.row.col.f32.bf16.bf16.f32 " \
        "{%0,%1,%2,%3}, {%4,%5,%6,%7}, {%8,%9}, {%0,%1,%2,%3};" \
        : "+f"((acc)[0]), "+f"((acc)[1]), "+f"((acc)[2]), "+f"((acc)[3]) \
        : "r"((a)[0]), "r"((a)[1]), "r"((a)[2]), "r"((a)[3]), "r"(b0v), "r"(b1v))
#define CP16(dst, src)      asm volatile("cp.async.cg.shared.global [%0], [%1], 16;" :: "r"(dst), "l"(src))
#define CP16Z(dst, src, sz) asm volatile("cp.async.cg.shared.global [%0], [%1], 16, %2;" :: "r"(dst), "l"(src), "r"(sz))
#define CPCOMMIT() asm volatile("cp.async.commit_group;" ::: "memory")
#define CPWAIT1()  asm volatile("cp.async.wait_group 1;" ::: "memory")
#define CPWAIT0()  asm volatile("cp.async.wait_group 0;" ::: "memory")

#define STG_BYTES 40960
#define MMA_SMEM  (2*STG_BYTES)
#define QK_SMEM   (4*128*72*2)
#define PV_STG    (2*128*40*2 + 2*64*40*2)
#define PV_SMEM   (2*PV_STG)

__device__ __forceinline__ void split_w(float x, bf16* oh, bf16* ol){
    bf16 hi = __float2bfloat16(x);
    *oh = hi;
    *ol = __float2bfloat16(x - __bfloat162float(hi));
}

// ---------------- small kernels ----------------

__global__ void k_ropetab(){
    int i = blockIdx.x*blockDim.x + threadIdx.x;
    if (i >= SQ*16) return;
    int j = i & 15, p = i >> 4;
    double ang = (double)p * pow(10000.0, -(double)j/16.0);
    g_cosT[i] = (float)cos(ang); g_sinT[i] = (float)sin(ang);
}

__global__ void k_embed(const int* __restrict__ ids, const float* __restrict__ emb){
    int t = blockIdx.x;
    const float* er = emb + (long)ids[t]*DM;
    for (int d = threadIdx.x; d < DM; d += 256){
        float vv = er[d];
        g_x[(long)t*4096+d] = vv; g_x[(long)t*4096+1024+d] = vv;
        g_x[(long)t*4096+2048+d] = vv; g_x[(long)t*4096+3072+d] = vv;
    }
}

__global__ void k_htrans(const float* __restrict__ src, float* __restrict__ dst, int nout){
    int i = blockIdx.x*blockDim.x + threadIdx.x;
    if (i >= 4096*nout) return;
    int r = i / nout, c = i % nout;
    dst[(long)c*4096 + r] = src[i];
}

// hc raw with fused per-token rms-inverse
template<int NOUT>
__global__ void __launch_bounds__(256) k_hcT(const float* __restrict__ Wt, const float* __restrict__ bb,
                                             float* __restrict__ raw){
    __shared__ float sx[16][129];
    __shared__ float sw[128][25];
    __shared__ float sinv[16];
    int t0 = blockIdx.x*16;
    int tid = threadIdx.x;
    int tt = tid & 15, jb = tid >> 4;
    float acc0 = 0.f, acc1 = 0.f, ss = 0.f;
    for (int k0 = 0; k0 < 4096; k0 += 128){
        for (int i = tid; i < 16*128; i += 256){
            int r = i>>7, c = i&127;
            sx[r][c] = g_x[(long)(t0+r)*4096 + k0 + c];
        }
        for (int i = tid; i < 128*NOUT; i += 256){
            int j = i>>7, kk = i&127;
            sw[kk][j] = Wt[(long)j*4096 + k0 + kk];
        }
        __syncthreads();
        #pragma unroll 8
        for (int kk = 0; kk < 128; kk++){
            float xv = sx[tt][kk];
            acc0 += xv*sw[kk][jb];
            if (NOUT > 16) acc1 += xv*sw[kk][jb+16];
            if (jb == 0) ss += xv*xv;
        }
        __syncthreads();
    }
    if (jb == 0) sinv[tt] = rsqrtf(ss/4096.f + 1e-6f);
    __syncthreads();
    float inv = sinv[tt];
    if (jb < NOUT)      raw[(long)(t0+tt)*NOUT + jb]      = inv*acc0 + bb[jb];
    if (NOUT > 16 && jb+16 < NOUT) raw[(long)(t0+tt)*NOUT + jb+16] = inv*acc1 + bb[jb+16];
}

__global__ void k_sink(){
    int t = blockIdx.x*blockDim.x + threadIdx.x;
    if (t >= SQ) return;
    const float* r = g_raw + (long)t*NCH;
    for (int n = 0; n < 4; n++){ g_pre[t*4+n] = 1.f + tanhf(r[n]); g_post[t*4+n] = 1.f + tanhf(r[4+n]); }
    float M[16]; float mx = -1e30f;
    #pragma unroll
    for (int i = 0; i < 16; i++){ float vv = r[8+i] + ((i%5==0)?1.f:0.f); M[i]=vv; if (vv>mx) mx=vv; }
    #pragma unroll
    for (int i = 0; i < 16; i++) M[i] = expf(M[i]-mx);
    for (int it = 0; it < 20; it++){
        #pragma unroll
        for (int n = 0; n < 4; n++){
            float s = M[n*4]+M[n*4+1]+M[n*4+2]+M[n*4+3] + 1e-6f;
            float rr = __frcp_rn(s);
            for (int m = 0; m < 4; m++) M[n*4+m] *= rr;
        }
        #pragma unroll
        for (int m = 0; m < 4; m++){
            float s = M[m]+M[4+m]+M[8+m]+M[12+m] + 1e-6f;
            float rr = __frcp_rn(s);
            for (int n = 0; n < 4; n++) M[n*4+m] *= rr;
        }
    }
    for (int i = 0; i < 16; i++) g_comb[t*16+i] = M[i];
}

// coll + rms + ln, writing fp32 h AND bf16 hi/lo split in one pass
__global__ void k_coll(const float* __restrict__ ln){
    int t = blockIdx.x;
    __shared__ float red[256];
    float p0=g_pre[t*4],p1=g_pre[t*4+1],p2=g_pre[t*4+2],p3=g_pre[t*4+3];
    const float* xt = g_x + (long)t*4096;
    float local[4]; float ss = 0.f;
    #pragma unroll
    for (int c = 0; c < 4; c++){
        int d = threadIdx.x + c*256;
        float vv = p0*xt[d]+p1*xt[1024+d]+p2*xt[2048+d]+p3*xt[3072+d];
        local[c]=vv; ss += vv*vv;
    }
    red[threadIdx.x]=ss; __syncthreads();
    for (int s = 128; s > 0; s >>= 1){ if (threadIdx.x < s) red[threadIdx.x]+=red[threadIdx.x+s]; __syncthreads(); }
    float inv = rsqrtf(red[0]/1024.f + 1e-6f);
    #pragma unroll
    for (int c = 0; c < 4; c++){
        int d = threadIdx.x + c*256;
        float vv = local[c]*inv*ln[d];
        g_h[(long)t*DM+d] = vv;
        split_w(vv, &g_ah[(long)t*DM+d], &g_al[(long)t*DM+d]);
    }
}

// rope + split q/k to bf16 hi/lo; reads fused qkv buffer [t][3072]
__global__ void k_rope_split(){
    int i = blockIdx.x*blockDim.x + threadIdx.x;
    if (i >= SQ*NHD*32) return;
    int j = i & 31, h = (i>>5)&15, s = i>>9;
    long base  = (long)s*HHD + h*64;          // output layout
    long baseq = (long)s*3*HHD + h*64;        // qkv input: q
    long basek = baseq + HHD;                 // k
    if (j < 16){
        float c = g_cosT[s*16+j], sn = g_sinT[s*16+j];
        float x1=g_qkv[baseq+j], x2=g_qkv[baseq+16+j];
        float q1 = x1*c-x2*sn, q2 = x1*sn+x2*c;
        split_w(q1, &g_qsh[base+j],    &g_qsl[base+j]);
        split_w(q2, &g_qsh[base+16+j], &g_qsl[base+16+j]);
        x1=g_qkv[basek+j]; x2=g_qkv[basek+16+j];
        q1 = x1*c-x2*sn; q2 = x1*sn+x2*c;
        split_w(q1, &g_ksh[base+j],    &g_ksl[base+j]);
        split_w(q2, &g_ksh[base+16+j], &g_ksl[base+16+j]);
    } else {
        int d1 = j + 16;   // 32..47
        int d2 = j + 32;   // 48..63
        split_w(g_qkv[baseq+d1], &g_qsh[base+d1], &g_qsl[base+d1]);
        split_w(g_qkv[basek+d1], &g_ksh[base+d1], &g_ksl[base+d1]);
        split_w(g_qkv[baseq+d2], &g_qsh[base+d2], &g_qsl[base+d2]);
        split_w(g_qkv[basek+d2], &g_ksh[base+d2], &g_ksl[base+d2]);
    }
}

// ---- HMMA scores: S[128q x 128k] per head, K=64, single stage ----
__global__ void __launch_bounds__(256) k_att_qk(){
    int h = blockIdx.z, q0 = (gridDim.y - 1 - blockIdx.y)*128, k0 = blockIdx.x*128;
    if (k0 > q0 + 127) return;
    extern __shared__ char dsm[];
    bf16* sQh = (bf16*)dsm;
    bf16* sQl = sQh + 128*72;
    bf16* sKh = sQl + 128*72;
    bf16* sKl = sKh + 128*72;
    int tid = threadIdx.x, wid = tid>>5, lane = tid&31;
    int r = tid>>1, cb = (tid&1)*32;
    #pragma unroll
    for (int j = 0; j < 4; j++){
        long qoff = (long)(q0+r)*HHD + h*64 + cb + j*8;
        long koff = (long)(k0+r)*HHD + h*64 + cb + j*8;
        CP16(smem_u32(&sQh[r*72 + cb + j*8]), g_qsh + qoff);
        CP16(smem_u32(&sQl[r*72 + cb + j*8]), g_qsl + qoff);
        CP16(smem_u32(&sKh[r*72 + cb + j*8]), g_ksh + koff);
        CP16(smem_u32(&sKl[r*72 + cb + j*8]), g_ksl + koff);
    }
    CPCOMMIT(); CPWAIT0();
    __syncthreads();
    int wm = (wid&3)*32, wn = (wid>>2)*64;
    float acc[2][8][4] = {};
    int qd = lane>>3, lr = lane&7;
    int aRow = lr + (qd&1)*8, aCol = (qd>>1)*8;
    int bRow = lr + (qd>>1)*8, bCol = (qd&1)*8;
    #pragma unroll
    for (int ks = 0; ks < 64; ks += 16){
        unsigned aH[2][4], aL[2][4];
        #pragma unroll
        for (int mt = 0; mt < 2; mt++){
            LDSM4(aH[mt], smem_u32(&sQh[(wm + mt*16 + aRow)*72 + ks + aCol]));
            LDSM4(aL[mt], smem_u32(&sQl[(wm + mt*16 + aRow)*72 + ks + aCol]));
        }
        #pragma unroll
        for (int np = 0; np < 4; np++){
            unsigned bH[4], bL[4];
            LDSM4(bH, smem_u32(&sKh[(wn + np*16 + bRow)*72 + ks + bCol]));
            LDSM4(bL, smem_u32(&sKl[(wn + np*16 + bRow)*72 + ks + bCol]));
            #pragma unroll
            for (int mt = 0; mt < 2; mt++){
                MMA16816(acc[mt][np*2],   aH[mt], bH[0], bH[1]);
                MMA16816(acc[mt][np*2+1], aH[mt], bH[2], bH[3]);
                MMA16816(acc[mt][np*2],   aH[mt], bL[0], bL[1]);
                MMA16816(acc[mt][np*2+1], aH[mt], bL[2], bL[3]);
                MMA16816(acc[mt][np*2],   aL[mt], bH[0], bH[1]);
                MMA16816(acc[mt][np*2+1], aL[mt], bH[2], bH[3]);
            }
        }
    }
    float* out = g_scr + (size_t)h*SQ*SQ;
    #pragma unroll
    for (int mt = 0; mt < 2; mt++){
        size_t row = q0 + wm + mt*16 + (lane>>2);
        #pragma unroll
        for (int nt = 0; nt < 8; nt++){
            size_t col = k0 + wn + nt*8 + (lane&3)*2;
            *(float2*)&out[row*SQ + col]     = make_float2(acc[mt][nt][0]*0.125f, acc[mt][nt][1]*0.125f);
            *(float2*)&out[(row+8)*SQ + col] = make_float2(acc[mt][nt][2]*0.125f, acc[mt][nt][3]*0.125f);
        }
    }
}

// softmax: fp32 scores -> bf16 hi/lo P, zero-filled to 128-tile end
__global__ void k_softmax2(){
    int h = blockIdx.y, qi = blockIdx.x;
    float* row = g_scr + (size_t)h*SQ*SQ + (size_t)qi*SQ;
    bf16* oh = g_ph + (size_t)h*SQ*SQ + (size_t)qi*SQ;
    bf16* ol = g_pl + (size_t)h*SQ*SQ + (size_t)qi*SQ;
    int n = qi + 1;
    __shared__ float red[256];
    float mx = -1e30f;
    for (int i = threadIdx.x; i < n; i += 256) mx = fmaxf(mx, row[i]);
    red[threadIdx.x]=mx; __syncthreads();
    for (int s = 128; s > 0; s >>= 1){ if (threadIdx.x < s) red[threadIdx.x]=fmaxf(red[threadIdx.x],red[threadIdx.x+s]); __syncthreads(); }
    mx = red[0]; __syncthreads();
    float sum = 0.f;
    for (int i = threadIdx.x; i < n; i += 256){ float e = expf(row[i]-mx); row[i]=e; sum+=e; }
    red[threadIdx.x]=sum; __syncthreads();
    for (int s = 128; s > 0; s >>= 1){ if (threadIdx.x < s) red[threadIdx.x]+=red[threadIdx.x+s]; __syncthreads(); }
    float invs = 1.f/red[0];
    for (int i = threadIdx.x; i < n; i += 256){
        float p = row[i]*invs;
        split_w(p, &oh[i], &ol[i]);
    }
    int end = ((qi>>7)+1)<<7;
    bf16 z = __float2bfloat16(0.f);
    for (int i = n + threadIdx.x; i < end; i += 256){ oh[i] = z; ol[i] = z; }
}

// ---- HMMA PV: O[128q x 64d] per head; A=P, B=Vt[d][seq]; 2-stage pipeline ----
__global__ void __launch_bounds__(256) k_att_pv(){
    int q0 = (gridDim.x - 1 - blockIdx.x)*128, h = blockIdx.y;
    extern __shared__ char dsm[];
    int tid = threadIdx.x, wid = tid>>5, lane = tid&31;
    int wm = wid*16;
    float acc[8][4] = {};
    int qd = lane>>3, lr = lane&7;
    int aRow = lr + (qd&1)*8, aCol = (qd>>1)*8;
    int bRow = lr + (qd>>1)*8, bCol = (qd&1)*8;
    int r0 = tid>>2, q0i = (tid&3)*8;
    int rb = tid>>2, cbv = (tid&3)*8;
    const bf16* Pbh = g_ph + (size_t)h*SQ*SQ;
    const bf16* Pbl = g_pl + (size_t)h*SQ*SQ;
    const bf16* Vbh = g_vth + (size_t)h*64*SQ;
    const bf16* Vbl = g_vtl + (size_t)h*64*SQ;

    #define PV_LOAD(s, kc) do { \
        bf16* _ph = (bf16*)(dsm + (s)*PV_STG); \
        bf16* _pl = (bf16*)(dsm + (s)*PV_STG + 10240); \
        bf16* _vh = (bf16*)(dsm + (s)*PV_STG + 20480); \
        bf16* _vl = (bf16*)(dsm + (s)*PV_STG + 25600); \
        CP16(smem_u32(&_ph[r0*40 + q0i]), Pbh + (size_t)(q0+r0)*SQ + (kc) + q0i); \
        CP16(smem_u32(&_ph[(r0+64)*40 + q0i]), Pbh + (size_t)(q0+r0+64)*SQ + (kc) + q0i); \
        CP16(smem_u32(&_pl[r0*40 + q0i]), Pbl + (size_t)(q0+r0)*SQ + (kc) + q0i); \
        CP16(smem_u32(&_pl[(r0+64)*40 + q0i]), Pbl + (size_t)(q0+r0+64)*SQ + (kc) + q0i); \
        CP16(smem_u32(&_vh[rb*40 + cbv]), Vbh + (size_t)rb*SQ + (kc) + cbv); \
        CP16(smem_u32(&_vl[rb*40 + cbv]), Vbl + (size_t)rb*SQ + (kc) + cbv); \
    } while(0)

    int nk = (q0 + 128) >> 5;
    PV_LOAD(0, 0);
    CPCOMMIT();
    for (int t = 0; t < nk; t++){
        int buf = t & 1;
        if (t+1 < nk){
            PV_LOAD(buf^1, (t+1)<<5);
            CPCOMMIT();
            CPWAIT1();
        } else {
            CPWAIT0();
        }
        __syncthreads();
        bf16* sPh = (bf16*)(dsm + buf*PV_STG);
        bf16* sPl = (bf16*)(dsm + buf*PV_STG + 10240);
        bf16* sVh = (bf16*)(dsm + buf*PV_STG + 20480);
        bf16* sVl = (bf16*)(dsm + buf*PV_STG + 25600);
        #pragma unroll
        for (int ks = 0; ks < 32; ks += 16){
            unsigned aH[4], aL[4];
            LDSM4(aH, smem_u32(&sPh[(wm + aRow)*40 + ks + aCol]));
            LDSM4(aL, smem_u32(&sPl[(wm + aRow)*40 + ks + aCol]));
            #pragma unroll
            for (int np = 0; np < 4; np++){
                unsigned bH[4], bL[4];
                LDSM4(bH, smem_u32(&sVh[(np*16 + bRow)*40 + ks + bCol]));
                LDSM4(bL, smem_u32(&sVl[(np*16 + bRow)*40 + ks + bCol]));
                MMA16816(acc[np*2],   aH, bH[0], bH[1]);
                MMA16816(acc[np*2+1], aH, bH[2], bH[3]);
                MMA16816(acc[np*2],   aH, bL[0], bL[1]);
                MMA16816(acc[np*2+1], aH, bL[2], bL[3]);
                MMA16816(acc[np*2],   aL, bH[0], bH[1]);
                MMA16816(acc[np*2+1], aL, bH[2], bH[3]);
            }
        }
        __syncthreads();
    }
    #undef PV_LOAD
    #pragma unroll
    for (int half = 0; half < 2; half++){
        long row = q0 + wm + half*8 + (lane>>2);
        #pragma unroll
        for (int nt = 0; nt < 8; nt++){
            long col = h*64 + nt*8 + (lane&3)*2;
            float v0 = acc[nt][half*2], v1 = acc[nt][half*2+1];
            split_w(v0, &g_aoh[row*HHD + col],   &g_aol[row*HHD + col]);
            split_w(v1, &g_aoh[row*HHD + col+1], &g_aol[row*HHD + col+1]);
        }
    }
}

// combine (+ optional MoE routed add fused)
__global__ void k_combine(int moe){
    int t = blockIdx.x;
    float ps[4], cb[16];
    #pragma unroll
    for (int n = 0; n < 4; n++) ps[n] = g_post[t*4+n];
    #pragma unroll
    for (int i = 0; i < 16; i++) cb[i] = g_comb[t*16+i];
    int e0 = 0, e1 = 0; float w0 = 0.f, w1 = 0.f;
    if (moe){
        e0 = g_eof[t*2]; e1 = g_eof[t*2+1];
        w0 = g_ew[t*2];  w1 = g_ew[t*2+1];
    }
    for (int d = threadIdx.x; d < DM; d += 256){
        float xv[4];
        #pragma unroll
        for (int n = 0; n < 4; n++) xv[n] = g_x[(long)t*4096 + n*1024 + d];
        float av = g_a[(long)t*DM + d];
        if (moe) av += w0*g_ed[(long)e0*DM+d] + w1*g_ed[(long)e1*DM+d];
        #pragma unroll
        for (int m = 0; m < 4; m++){
            float s = ps[m]*av;
            #pragma unroll
            for (int n = 0; n < 4; n++) s += cb[n*4+m]*xv[n];
            g_x[(long)t*4096 + m*1024 + d] = s;
        }
    }
}

__global__ void k_reset(){
    int i = blockIdx.x*blockDim.x + threadIdx.x;
    if (i < NEXP){ g_cnt[i]=0; g_fill[i]=0; }
    if (i < MAXENT) g_etok[i] = -1;
}

__global__ void k_gate(const float* __restrict__ gw, const int* __restrict__ ids,
                       const int* __restrict__ t2e, int layer){
    int t = blockIdx.x;
    __shared__ float sm[256][8];
    __shared__ float sc[8];
    float acc[8] = {};
    const float* xt = g_h + (long)t*DM;
    for (int i = threadIdx.x; i < DM; i += 256){
        float vv = xt[i];
        #pragma unroll
        for (int e = 0; e < 8; e++) acc[e] += vv*gw[e*DM+i];
    }
    #pragma unroll
    for (int e = 0; e < 8; e++) sm[threadIdx.x][e] = acc[e];
    __syncthreads();
    if (threadIdx.x < 8){
        float s = 0.f;
        for (int r = 0; r < 256; r++) s += sm[r][threadIdx.x];
        float sp = (s > 20.f) ? s : log1pf(expf(s));
        sc[threadIdx.x] = sqrtf(sp);
    }
    __syncthreads();
    if (threadIdx.x == 0){
        int i0, i1;
        if (layer < 1){ int id = ids[t]; i0 = t2e[id*2]; i1 = t2e[id*2+1]; }
        else {
            i0 = 0;
            for (int e = 1; e < 8; e++) if (sc[e] > sc[i0]) i0 = e;
            i1 = -1; float best = -1e30f;
            for (int e = 0; e < 8; e++){ if (e==i0) continue; if (sc[e] > best){ best = sc[e]; i1 = e; } }
        }
        float w0 = sc[i0], w1 = sc[i1];
        float sw = w0 + w1 + 1e-20f;
        g_ew[t*2] = w0/sw*2.5f; g_ew[t*2+1] = w1/sw*2.5f;
        g_eidx[t*2] = i0; g_eidx[t*2+1] = i1;
        atomicAdd(&g_cnt[i0], 1); atomicAdd(&g_cnt[i1], 1);
    }
}

__global__ void k_off(){
    if (threadIdx.x == 0){
        int o = 0;
        for (int e = 0; e < NEXP; e++){ g_off[e] = o; o += ((g_cnt[e]+127)/128)*128; }
        g_off[NEXP] = o;
    }
}

__global__ void k_scatter(){
    int i = blockIdx.x*blockDim.x + threadIdx.x;
    if (i >= SQ*KSEL) return;
    int e = g_eidx[i];
    int pos = g_off[e] + atomicAdd(&g_fill[e], 1);
    g_etok[pos] = i >> 1;
    g_eof[i] = pos;
}

// silu on fused gate/up layout: src[ent][1024] (g: 0..511, u: 512..1023) -> out[ent][512] split
__global__ void k_silu_split2(const float* __restrict__ src,
                              bf16* __restrict__ oh, bf16* __restrict__ ol, int n){
    int i = blockIdx.x*blockDim.x + threadIdx.x;
    if (i >= n) return;
    long ent = i >> 9;
    int f = i & 511;
    float x = src[ent*1024 + f];
    float u = src[ent*1024 + 512 + f];
    float s = (x / (1.f + expf(-x))) * u;
    split_w(s, &oh[i], &ol[i]);
}

// transpose + split: src [K][N] fp32 (row stride sstr, z-stride K*N) -> dst [N][K] bf16 hi/lo (z-stride dstZ)
__global__ void k_tsplit(const float* __restrict__ src, bf16* __restrict__ dh, bf16* __restrict__ dl,
                         int K, int N, int sstr, long dstZ){
    src += (long)blockIdx.z * K * N;
    dh  += (long)blockIdx.z * dstZ;
    dl  += (long)blockIdx.z * dstZ;
    __shared__ float t[32][33];
    int n0 = blockIdx.x*32, k0 = blockIdx.y*32;
    int tx = threadIdx.x, ty = threadIdx.y;
    #pragma unroll
    for (int j = 0; j < 4; j++)
        t[ty + j*8][tx] = src[(long)(k0 + ty + j*8)*sstr + n0 + tx];
    __syncthreads();
    int k2 = (tx & 15)*2, half = tx >> 4;
    #pragma unroll
    for (int j = 0; j < 2; j++){
        int nn = ty + j*8 + half*16;
        float f0 = t[k2][nn],   f1 = t[k2+1][nn];
        bf16 h0 = __float2bfloat16(f0), h1 = __float2bfloat16(f1);
        bf16 l0 = __float2bfloat16(f0 - __bfloat162float(h0));
        bf16 l1 = __float2bfloat16(f1 - __bfloat162float(h1));
        long o = (long)(n0 + nn)*K + k0 + k2;
        __nv_bfloat162 hv; hv.x = h0; hv.y = h1;
        __nv_bfloat162 lv; lv.x = l0; lv.y = l1;
        *(__nv_bfloat162*)&dh[o] = hv;
        *(__nv_bfloat162*)&dl[o] = lv;
    }
}

// final head collapse + rms + final_norm, writing split bf16 directly
__global__ void k_final(const float* __restrict__ fw){
    int t = blockIdx.x;
    __shared__ float red[256];
    float p[4];
    #pragma unroll
    for (int n = 0; n < 4; n++) p[n] = 1.f + tanhf(g_raw[t*4+n]);
    const float* xt = g_x + (long)t*4096;
    float local[4]; float ss = 0.f;
    #pragma unroll
    for (int c = 0; c < 4; c++){
        int d = threadIdx.x + c*256;
        float vv = p[0]*xt[d]+p[1]*xt[1024+d]+p[2]*xt[2048+d]+p[3]*xt[3072+d];
        local[c]=vv; ss += vv*vv;
    }
    red[threadIdx.x]=ss; __syncthreads();
    for (int s = 128; s > 0; s >>= 1){ if (threadIdx.x < s) red[threadIdx.x]+=red[threadIdx.x+s]; __syncthreads(); }
    float inv = rsqrtf(red[0]/1024.f + 1e-6f);
    #pragma unroll
    for (int c = 0; c < 4; c++){
        int d = threadIdx.x + c*256;
        float vv = local[c]*inv*fw[d];
        split_w(vv, &g_ah[(long)t*DM+d], &g_al[(long)t*DM+d]);
    }
}

// ---------------- pipelined HMMA GEMM: C[M,N] = A[M,K] x B[N,K]^T ----------------
__global__ void __launch_bounds__(256) k_mma(const bf16* __restrict__ Ah, const bf16* __restrict__ Al,
                                             const bf16* __restrict__ Bh, const bf16* __restrict__ Bl,
                                             float* __restrict__ C, int N, int K){
    extern __shared__ char dsm[];
    int tid = threadIdx.x, wid = tid>>5, lane = tid&31;
    int m0 = blockIdx.y*128, n0 = blockIdx.x*128;
    int wm = (wid&3)*32, wn = (wid>>2)*64;
    float acc[2][8][4] = {};
    int qd = lane>>3, lr = lane&7;
    int aRow = lr + (qd&1)*8, aCol = (qd>>1)*8;
    int bRow = lr + (qd>>1)*8, bCol = (qd&1)*8;
    int r0 = tid>>2, q0i = (tid&3)*8;
    int r1 = r0 + 64;

    #define LOAD_STAGE(s, kc) do { \
        bf16* _ah = (bf16*)(dsm + (s)*STG_BYTES); \
        bf16* _al = (bf16*)(dsm + (s)*STG_BYTES + 10240); \
        bf16* _bh = (bf16*)(dsm + (s)*STG_BYTES + 20480); \
        bf16* _bl = (bf16*)(dsm + (s)*STG_BYTES + 30720); \
        CP16(smem_u32(&_ah[r0*40 + q0i]), Ah + (long)(m0+r0)*K + (kc) + q0i); \
        CP16(smem_u32(&_ah[r1*40 + q0i]), Ah + (long)(m0+r1)*K + (kc) + q0i); \
        CP16(smem_u32(&_al[r0*40 + q0i]), Al + (long)(m0+r0)*K + (kc) + q0i); \
        CP16(smem_u32(&_al[r1*40 + q0i]), Al + (long)(m0+r1)*K + (kc) + q0i); \
        CP16(smem_u32(&_bh[r0*40 + q0i]), Bh + (long)(n0+r0)*K + (kc) + q0i); \
        CP16(smem_u32(&_bh[r1*40 + q0i]), Bh + (long)(n0+r1)*K + (kc) + q0i); \
        CP16(smem_u32(&_bl[r0*40 + q0i]), Bl + (long)(n0+r0)*K + (kc) + q0i); \
        CP16(smem_u32(&_bl[r1*40 + q0i]), Bl + (long)(n0+r1)*K + (kc) + q0i); \
    } while(0)

    LOAD_STAGE(0, 0);
    CPCOMMIT();
    int nk = K >> 5;
    for (int t = 0; t < nk; t++){
        int buf = t & 1;
        if (t+1 < nk){
            LOAD_STAGE(buf^1, (t+1)<<5);
            CPCOMMIT();
            CPWAIT1();
        } else {
            CPWAIT0();
        }
        __syncthreads();
        bf16* sAh = (bf16*)(dsm + buf*STG_BYTES);
        bf16* sAl = (bf16*)(dsm + buf*STG_BYTES + 10240);
        bf16* sBh = (bf16*)(dsm + buf*STG_BYTES + 20480);
        bf16* sBl = (bf16*)(dsm + buf*STG_BYTES + 30720);
        #pragma unroll
        for (int ks = 0; ks < 32; ks += 16){
            unsigned aH[2][4], aL[2][4];
            #pragma unroll
            for (int mt = 0; mt < 2; mt++){
                LDSM4(aH[mt], smem_u32(&sAh[(wm + mt*16 + aRow)*40 + ks + aCol]));
                LDSM4(aL[mt], smem_u32(&sAl[(wm + mt*16 + aRow)*40 + ks + aCol]));
            }
            #pragma unroll
            for (int np = 0; np < 4; np++){
                unsigned bH[4], bL[4];
                LDSM4(bH, smem_u32(&sBh[(wn + np*16 + bRow)*40 + ks + bCol]));
                LDSM4(bL, smem_u32(&sBl[(wn + np*16 + bRow)*40 + ks + bCol]));
                #pragma unroll
                for (int mt = 0; mt < 2; mt++){
                    MMA16816(acc[mt][np*2],   aH[mt], bH[0], bH[1]);
                    MMA16816(acc[mt][np*2+1], aH[mt], bH[2], bH[3]);
                    MMA16816(acc[mt][np*2],   aH[mt], bL[0], bL[1]);
                    MMA16816(acc[mt][np*2+1], aH[mt], bL[2], bL[3]);
                    MMA16816(acc[mt][np*2],   aL[mt], bH[0], bH[1]);
                    MMA16816(acc[mt][np*2+1], aL[mt], bH[2], bH[3]);
                }
            }
        }
        __syncthreads();
    }
    #undef LOAD_STAGE
    #pragma unroll
    for (int mt = 0; mt < 2; mt++){
        long row = m0 + wm + mt*16 + (lane>>2);
        #pragma unroll
        for (int nt = 0; nt < 8; nt++){
            long col = n0 + wn + nt*8 + (lane&3)*2;
            *(float2*)&C[row*N + col]     = make_float2(acc[mt][nt][0], acc[mt][nt][1]);
            *(float2*)&C[(row+8)*N + col] = make_float2(acc[mt][nt][2], acc[mt][nt][3]);
        }
    }
}

// pipelined segmented (per-expert) HMMA GEMM with optional token gather on A
__global__ void __launch_bounds__(256) k_mma_seg(const bf16* __restrict__ Ah, const bf16* __restrict__ Al,
                                                 const bf16* __restrict__ Bh0, const bf16* __restrict__ Bl0,
                                                 float* __restrict__ C, int N, int K, long Bstride, int useGather){
    int e = blockIdx.z;
    int seg0 = g_off[e], nrows = g_cnt[e];
    int m0 = blockIdx.y*128;
    if (m0 >= nrows) return;
    int n0 = blockIdx.x*128;
    const bf16* Bh = Bh0 + (long)e*Bstride;
    const bf16* Bl = Bl0 + (long)e*Bstride;
    extern __shared__ char dsm[];
    int tid = threadIdx.x, wid = tid>>5, lane = tid&31;
    int wm = (wid&3)*32, wn = (wid>>2)*64;
    float acc[2][8][4] = {};
    int qd = lane>>3, lr = lane&7;
    int aRow = lr + (qd&1)*8, aCol = (qd>>1)*8;
    int bRow = lr + (qd>>1)*8, bCol = (qd&1)*8;
    int r0 = tid>>2, q0i = (tid&3)*8;
    int r1 = r0 + 64;
    const bf16 *a0h, *a0l, *a1h, *a1l;
    unsigned sz0 = 16, sz1 = 16;
    {
        int ge0 = seg0 + m0 + r0, ge1 = seg0 + m0 + r1;
        if (useGather){
            int tk0 = g_etok[ge0], tk1 = g_etok[ge1];
            if (tk0 >= 0){ a0h = Ah + (long)tk0*K; a0l = Al + (long)tk0*K; } else { a0h = Ah; a0l = Al; sz0 = 0; }
            if (tk1 >= 0){ a1h = Ah + (long)tk1*K; a1l = Al + (long)tk1*K; } else { a1h = Ah; a1l = Al; sz1 = 0; }
        } else {
            a0h = Ah + (long)ge0*K; a0l = Al + (long)ge0*K;
            a1h = Ah + (long)ge1*K; a1l = Al + (long)ge1*K;
        }
    }

    #define LOAD_STAGE_S(s, kc) do { \
        bf16* _ah = (bf16*)(dsm + (s)*STG_BYTES); \
        bf16* _al = (bf16*)(dsm + (s)*STG_BYTES + 10240); \
        bf16* _bh = (bf16*)(dsm + (s)*STG_BYTES + 20480); \
        bf16* _bl = (bf16*)(dsm + (s)*STG_BYTES + 30720); \
        CP16Z(smem_u32(&_ah[r0*40 + q0i]), a0h + (kc) + q0i, sz0); \
        CP16Z(smem_u32(&_ah[r1*40 + q0i]), a1h + (kc) + q0i, sz1); \
        CP16Z(smem_u32(&_al[r0*40 + q0i]), a0l + (kc) + q0i, sz0); \
        CP16Z(smem_u32(&_al[r1*40 + q0i]), a1l + (kc) + q0i, sz1); \
        CP16(smem_u32(&_bh[r0*40 + q0i]), Bh + (long)(n0+r0)*K + (kc) + q0i); \
        CP16(smem_u32(&_bh[r1*40 + q0i]), Bh + (long)(n0+r1)*K + (kc) + q0i); \
        CP16(smem_u32(&_bl[r0*40 + q0i]), Bl + (long)(n0+r0)*K + (kc) + q0i); \
        CP16(smem_u32(&_bl[r1*40 + q0i]), Bl + (long)(n0+r1)*K + (kc) + q0i); \
    } while(0)

    LOAD_STAGE_S(0, 0);
    CPCOMMIT();
    int nk = K >> 5;
    for (int t = 0; t < nk; t++){
        int buf = t & 1;
        if (t+1 < nk){
            LOAD_STAGE_S(buf^1, (t+1)<<5);
            CPCOMMIT();
            CPWAIT1();
        } else {
            CPWAIT0();
        }
        __syncthreads();
        bf16* sAh = (bf16*)(dsm + buf*STG_BYTES);
        bf16* sAl = (bf16*)(dsm + buf*STG_BYTES + 10240);
        bf16* sBh = (bf16*)(dsm + buf*STG_BYTES + 20480);
        bf16* sBl = (bf16*)(dsm + buf*STG_BYTES + 30720);
        #pragma unroll
        for (int ks = 0; ks < 32; ks += 16){
            unsigned aH[2][4], aL[2][4];
            #pragma unroll
            for (int mt = 0; mt < 2; mt++){
                LDSM4(aH[mt], smem_u32(&sAh[(wm + mt*16 + aRow)*40 + ks + aCol]));
                LDSM4(aL[mt], smem_u32(&sAl[(wm + mt*16 + aRow)*40 + ks + aCol]));
            }
            #pragma unroll
            for (int np = 0; np < 4; np++){
                unsigned bH[4], bL[4];
                LDSM4(bH, smem_u32(&sBh[(wn + np*16 + bRow)*40 + ks + bCol]));
                LDSM4(bL, smem_u32(&sBl[(wn + np*16 + bRow)*40 + ks + bCol]));
                #pragma unroll
                for (int mt = 0; mt < 2; mt++){
                    MMA16816(acc[mt][np*2],   aH[mt], bH[0], bH[1]);
                    MMA16816(acc[mt][np*2+1], aH[mt], bH[2], bH[3]);
                    MMA16816(acc[mt][np*2],   aH[mt], bL[0], bL[1]);
                    MMA16816(acc[mt][np*2+1], aH[mt], bL[2], bL[3]);
                    MMA16816(acc[mt][np*2],   aL[mt], bH[0], bH[1]);
                    MMA16816(acc[mt][np*2+1], aL[mt], bH[2], bH[3]);
                }
            }
        }
        __syncthreads();
    }
    #undef LOAD_STAGE_S
    #pragma unroll
    for (int mt = 0; mt < 2; mt++){
        long row = seg0 + m0 + wm + mt*16 + (lane>>2);
        #pragma unroll
        for (int nt = 0; nt < 8; nt++){
            long col = n0 + wn + nt*8 + (lane&3)*2;
            *(float2*)&C[row*N + col]     = make_float2(acc[mt][nt][0], acc[mt][nt][1]);
            *(float2*)&C[(row+8)*N + col] = make_float2(acc[mt][nt][2], acc[mt][nt][3]);
        }
    }
}

static float* SYM(const void* symbol){
    void* p = nullptr;
    cudaGetSymbolAddress(&p, symbol);
    return (float*)p;
}

extern "C" void kernel_launch(void* const* d_in, const int* in_sizes, int n_in,
                              void* d_out, int out_size){
    const int*   ids    = (const int*)d_in[0];
    const int*   t2e    = (const int*)d_in[1];
    const float* embed  = (const float*)d_in[2];
    const float* ahw    = (const float*)d_in[3];
    const float* ahb    = (const float*)d_in[4];
    const float* fhw    = (const float*)d_in[5];
    const float* fhb    = (const float*)d_in[6];
    const float* ln1    = (const float*)d_in[7];
    const float* ln2    = (const float*)d_in[8];
    const float* wq     = (const float*)d_in[9];
    const float* wk     = (const float*)d_in[10];
    const float* wv     = (const float*)d_in[11];
    const float* wo     = (const float*)d_in[12];
    const float* gatew  = (const float*)d_in[13];
    const float* wge    = (const float*)d_in[14];
    const float* wue    = (const float*)d_in[15];
    const float* wde    = (const float*)d_in[16];
    const float* wgs    = (const float*)d_in[17];
    const float* wus    = (const float*)d_in[18];
    const float* wds    = (const float*)d_in[19];
    const float* headw  = (const float*)d_in[20];
    const float* headb  = (const float*)d_in[21];
    const float* fnw    = (const float*)d_in[22];
    const float* lmh    = (const float*)d_in[23];
    float* out = (float*)d_out;

    float* ph    = SYM(g_h);
    float* pqkv  = SYM(g_qkv);
    float* pa    = SYM(g_a);
    float* peg   = SYM(g_eg);
    float* ped   = SYM(g_ed);
    float* ps1   = SYM(g_s1);
    float* praw  = SYM(g_raw);
    float* ptah  = SYM(t_ahw);
    float* ptfh  = SYM(t_fhw);
    float* pthw  = SYM(t_hw);
    bf16* pah  = (bf16*)SYM(g_ah);   bf16* pal  = (bf16*)SYM(g_al);
    bf16* paoh = (bf16*)SYM(g_aoh);  bf16* paol = (bf16*)SYM(g_aol);
    bf16* ps1h = (bf16*)SYM(g_s1h);  bf16* ps1l = (bf16*)SYM(g_s1l);
    bf16* pegh = (bf16*)SYM(g_egh);  bf16* pegl = (bf16*)SYM(g_egl);
    bf16* pvth = (bf16*)SYM(g_vth);  bf16* pvtl = (bf16*)SYM(g_vtl);
    bf16* pbh  = (bf16*)SYM(g_bh);   bf16* pbl  = (bf16*)SYM(g_bl);
    bf16* pqkvh = (bf16*)SYM(twqkvh); bf16* pqkvl = (bf16*)SYM(twqkvl);
    bf16* poh  = (bf16*)SYM(twoh);   bf16* pol  = (bf16*)SYM(twol);
    bf16* pgush = (bf16*)SYM(twgush); bf16* pgusl = (bf16*)SYM(twgusl);
    bf16* pdsh = (bf16*)SYM(twdsh);  bf16* pdsl = (bf16*)SYM(twdsl);
    bf16* pgueh = (bf16*)SYM(twgueh); bf16* pguel = (bf16*)SYM(twguel);
    bf16* pdeh = (bf16*)SYM(twdeh);  bf16* pdel = (bf16*)SYM(twdel);

    cudaFuncSetAttribute(k_mma,     cudaFuncAttributeMaxDynamicSharedMemorySize, MMA_SMEM);
    cudaFuncSetAttribute(k_mma_seg, cudaFuncAttributeMaxDynamicSharedMemorySize, MMA_SMEM);
    cudaFuncSetAttribute(k_att_qk,  cudaFuncAttributeMaxDynamicSharedMemorySize, QK_SMEM);
    cudaFuncSetAttribute(k_att_pv,  cudaFuncAttributeMaxDynamicSharedMemorySize, PV_SMEM);

    dim3 tb(32,8);
    // ---- weight prep ----
    k_tsplit<<<dim3(VOC/32, DM/32), tb>>>(lmh, pbh, pbl, DM, VOC, VOC, 0);
    for (int l = 0; l < NLAY; l++){
        long o1 = (long)l*DM*HHD, oS = (long)l*FF*DM, oE = (long)l*NEXP*DM*FF;
        long oQKV = (long)l*3*HHD*DM, oGUS = (long)l*1024*DM, oGUE = (long)l*NEXP*1024*DM;
        // fused QKV weights [3072][DM]
        k_tsplit<<<dim3(32,32), tb>>>(wq + o1, pqkvh + oQKV,                 pqkvl + oQKV,                 DM, HHD, HHD, 0);
        k_tsplit<<<dim3(32,32), tb>>>(wk + o1, pqkvh + oQKV + (long)HHD*DM,  pqkvl + oQKV + (long)HHD*DM,  DM, HHD, HHD, 0);
        k_tsplit<<<dim3(32,32), tb>>>(wv + o1, pqkvh + oQKV + (long)2*HHD*DM,pqkvl + oQKV + (long)2*HHD*DM,DM, HHD, HHD, 0);
        k_tsplit<<<dim3(32,32), tb>>>(wo + o1, poh + o1, pol + o1, HHD, DM, DM, 0);
        // fused shared gate/up [1024][DM]
        k_tsplit<<<dim3(16,32), tb>>>(wgs + oS, pgush + oGUS,                pgusl + oGUS,                DM, FF, FF, 0);
        k_tsplit<<<dim3(16,32), tb>>>(wus + oS, pgush + oGUS + (long)FF*DM,  pgusl + oGUS + (long)FF*DM,  DM, FF, FF, 0);
        k_tsplit<<<dim3(32,16), tb>>>(wds + oS, pdsh + oS, pdsl + oS, FF, DM, DM, 0);
        // fused expert gate/up [E][1024][DM]
        k_tsplit<<<dim3(16,32,8), tb>>>(wge + oE, pgueh + oGUE,               pguel + oGUE,               DM, FF, FF, (long)1024*DM);
        k_tsplit<<<dim3(16,32,8), tb>>>(wue + oE, pgueh + oGUE + (long)FF*DM, pguel + oGUE + (long)FF*DM, DM, FF, FF, (long)1024*DM);
        k_tsplit<<<dim3(32,16,8), tb>>>(wde + oE, pdeh + oE, pdel + oE, FF, DM, DM, (long)FF*DM);
        k_htrans<<<(4096*NCH+255)/256, 256>>>(ahw + (long)l*4096*NCH, ptah + (long)l*NCH*4096, NCH);
        k_htrans<<<(4096*NCH+255)/256, 256>>>(fhw + (long)l*4096*NCH, ptfh + (long)l*NCH*4096, NCH);
    }
    k_htrans<<<(4096*4+255)/256, 256>>>(headw, pthw, 4);

    k_ropetab<<<(SQ*16+255)/256, 256>>>();
    k_embed<<<SQ, 256>>>(ids, embed);

    dim3 gm_qkv(24, 16);     // N=3072
    dim3 gm_1024(8, 16);
    dim3 gm_gus (8, 16);     // N=1024 (fused shared gate/up)
    dim3 gms_gu (8, MAXENT/128, 8);   // N=1024 fused expert gate/up
    dim3 gms_dm (8, MAXENT/128, 8);
    dim3 gqk(16, 16, 16);
    dim3 gsm(SQ, 16);
    dim3 gpv(16, 16);

    for (int l = 0; l < NLAY; l++){
        long o1 = (long)l*DM*HHD, oS = (long)l*FF*DM;
        long oQKV = (long)l*3*HHD*DM, oGUS = (long)l*1024*DM, oGUE = (long)l*NEXP*1024*DM, oDE = (long)l*NEXP*DM*FF;
        // attention block
        k_hcT<NCH><<<SQ/16, 256>>>(ptah + (long)l*NCH*4096, ahb + l*NCH, praw);
        k_sink<<<(SQ+255)/256, 256>>>();
        k_coll<<<SQ, 256>>>(ln1 + l*DM);
        k_mma<<<gm_qkv, 256, MMA_SMEM>>>(pah, pal, pqkvh + oQKV, pqkvl + oQKV, pqkv, 3*HHD, DM);
        k_rope_split<<<(SQ*NHD*32+255)/256, 256>>>();
        k_tsplit<<<dim3(HHD/32, SQ/32), tb>>>(pqkv + 2*HHD, pvth, pvtl, SQ, HHD, 3*HHD, 0);
        k_att_qk<<<gqk, 256, QK_SMEM>>>();
        k_softmax2<<<gsm, 256>>>();
        k_att_pv<<<gpv, 256, PV_SMEM>>>();
        k_mma<<<gm_1024, 256, MMA_SMEM>>>(paoh, paol, poh + o1, pol + o1, pa, DM, HHD);
        k_combine<<<SQ, 256>>>(0);
        // ffn block
        k_hcT<NCH><<<SQ/16, 256>>>(ptfh + (long)l*NCH*4096, fhb + l*NCH, praw);
        k_sink<<<(SQ+255)/256, 256>>>();
        k_coll<<<SQ, 256>>>(ln2 + l*DM);
        k_reset<<<(MAXENT+255)/256, 256>>>();
        k_gate<<<SQ, 256>>>(gatew + (long)l*NEXP*DM, ids, t2e, l);
        k_off<<<1, 32>>>();
        k_scatter<<<(SQ*KSEL+255)/256, 256>>>();
        k_mma_seg<<<gms_gu, 256, MMA_SMEM>>>(pah, pal, pgueh + oGUE, pguel + oGUE, peg, 1024, DM, (long)1024*DM, 1);
        k_silu_split2<<<((long)MAXENT*FF+255)/256, 256>>>(peg, pegh, pegl, MAXENT*FF);
        k_mma_seg<<<gms_dm, 256, MMA_SMEM>>>(pegh, pegl, pdeh + oDE, pdel + oDE, ped, DM, FF, (long)FF*DM, 0);
        k_mma<<<gm_gus, 256, MMA_SMEM>>>(pah, pal, pgush + oGUS, pgusl + oGUS, ps1, 1024, DM);
        k_silu_split2<<<(SQ*FF+255)/256, 256>>>(ps1, ps1h, ps1l, SQ*FF);
        k_mma<<<gm_1024, 256, MMA_SMEM>>>(ps1h, ps1l, pdsh + oS, pdsl + oS, pa, DM, FF);
        k_combine<<<SQ, 256>>>(1);
    }

    // final head + lm head
    k_hcT<4><<<SQ/16, 256>>>(pthw, headb, praw);
    k_final<<<SQ, 256>>>(fnw);
    dim3 glm(VOC/128, SQ/128);
    k_mma<<<glm, 256, MMA_SMEM>>>(pah, pal, pbh, pbl, out, VOC, DM);
}